// round 1
// baseline (speedup 1.0000x reference)
#include <cuda_runtime.h>
#include <math.h>

#define FULLMASK 0xffffffffu

// ---------------- problem constants ----------------
constexpr int Bb = 2, Ss = 2048, Dd = 2048;
constexpr int Zz = 512, HDim = 4096, Hh = 8, EN = 8;
constexpr int ZH = 64, VH = 512;
constexpr int Gg = 32, DG = 64;
constexpr int BHh = Bb * Hh;
constexpr float EPSC = 1e-5f;

// ---------------- scratch (device globals; no allocation allowed) ----------------
__device__ float g_tsn [Bb * Ss * Dd];
__device__ float g_cema[Bb * Ss * Dd];
__device__ float g_mx  [Bb * Ss * Dd];
__device__ float g_z   [Bb * Ss * Zz];
__device__ float g_q   [BHh * Ss * ZH];
__device__ float g_k   [BHh * Ss * ZH];
__device__ float g_v   [Bb * Ss * HDim];
__device__ float g_r   [Bb * Ss * HDim];
__device__ float g_attn[Bb * Ss * HDim];
__device__ float g_scores[(size_t)BHh * Ss * Ss];   // raw scores, then probs in-place
__device__ float g_p1[Bb * Gg * Ss];
__device__ float g_p2[Bb * Gg * Ss];
__device__ float g_c1[Bb * Gg * Ss];
__device__ float g_c2[Bb * Gg * Ss];
__device__ float g_coef[6][Dd * EN];

// ---------------- helpers ----------------
__device__ __forceinline__ float sigmoidf_(float x) { return 1.f / (1.f + __expf(-x)); }

// ==================================================================
// Timestep norm: stage 1 — per (b,s,g) partial sum / sumsq (1 warp each)
// ==================================================================
__global__ void tsn_partial(const float* __restrict__ x) {
    int warp = (blockIdx.x * blockDim.x + threadIdx.x) >> 5;
    int lane = threadIdx.x & 31;
    if (warp >= Bb * Ss * Gg) return;
    int g = warp % Gg;
    int s = (warp / Gg) % Ss;
    int b = warp / (Gg * Ss);
    const float* p = x + ((size_t)(b * Ss + s)) * Dd + g * DG;
    float v0 = p[lane], v1 = p[lane + 32];
    float s1 = v0 + v1;
    float s2 = v0 * v0 + v1 * v1;
    #pragma unroll
    for (int o = 16; o; o >>= 1) {
        s1 += __shfl_down_sync(FULLMASK, s1, o);
        s2 += __shfl_down_sync(FULLMASK, s2, o);
    }
    if (lane == 0) {
        int idx = (b * Gg + g) * Ss + s;
        g_p1[idx] = s1;
        g_p2[idx] = s2;
    }
}

// ==================================================================
// Timestep norm: stage 2 — inclusive prefix scan over S per (b,g)
// one block (256 threads) per (b,g); 8 elems per thread + block scan
// ==================================================================
__global__ void tsn_scan() {
    int bg = blockIdx.x;
    int t  = threadIdx.x;
    const float* r1 = g_p1 + bg * Ss;
    const float* r2 = g_p2 + bg * Ss;
    float v1[8], v2[8];
    float a1 = 0.f, a2 = 0.f;
    #pragma unroll
    for (int i = 0; i < 8; i++) {
        a1 += r1[t * 8 + i]; v1[i] = a1;
        a2 += r2[t * 8 + i]; v2[i] = a2;
    }
    __shared__ float sh1[256], sh2[256];
    sh1[t] = a1; sh2[t] = a2;
    __syncthreads();
    for (int off = 1; off < 256; off <<= 1) {
        float b1 = 0.f, b2 = 0.f;
        if (t >= off) { b1 = sh1[t - off]; b2 = sh2[t - off]; }
        __syncthreads();
        sh1[t] += b1; sh2[t] += b2;
        __syncthreads();
    }
    float o1 = t ? sh1[t - 1] : 0.f;
    float o2 = t ? sh2[t - 1] : 0.f;
    float* w1 = g_c1 + bg * Ss;
    float* w2 = g_c2 + bg * Ss;
    #pragma unroll
    for (int i = 0; i < 8; i++) {
        w1[t * 8 + i] = v1[i] + o1;
        w2[t * 8 + i] = v2[i] + o2;
    }
}

// ==================================================================
// Timestep norm: stage 3 — elementwise normalize (float4)
// ==================================================================
__global__ void tsn_norm(const float* __restrict__ x, const float* __restrict__ w,
                         const float* __restrict__ bias) {
    int i4 = blockIdx.x * blockDim.x + threadIdx.x;
    if (i4 >= Bb * Ss * Dd / 4) return;
    int d4 = i4 % (Dd / 4);
    int s  = (i4 / (Dd / 4)) % Ss;
    int b  = i4 / (Dd / 4 * Ss);
    int d  = d4 * 4;
    int g  = d / DG;
    int ci = (b * Gg + g) * Ss + s;
    float cnt  = (float)(s + 1) * (float)DG;
    float mean = g_c1[ci] / cnt;
    float var  = g_c2[ci] / cnt - mean * mean;
    float inv  = rsqrtf(var + EPSC);
    float4 xv = *(const float4*)(x + (size_t)i4 * 4);
    float4 wv = *(const float4*)(w + d);
    float4 bv = *(const float4*)(bias + d);
    float4 o;
    o.x = (xv.x - mean) * inv * wv.x + bv.x;
    o.y = (xv.y - mean) * inv * wv.y + bv.y;
    o.z = (xv.z - mean) * inv * wv.z + bv.z;
    o.w = (xv.w - mean) * inv * wv.w + bv.w;
    *(float4*)(g_tsn + (size_t)i4 * 4) = o;
}

// ==================================================================
// CEMA coefficient precompute (D*EN threads)
// ==================================================================
__global__ void cema_coef(const float* __restrict__ alpha, const float* __restrict__ delta,
                          const float* __restrict__ theta, const float* __restrict__ gamma) {
    int i = blockIdx.x * blockDim.x + threadIdx.x;
    if (i >= Dd * EN) return;
    int d = i / EN, n = i % EN;
    float p  = 1.f / (1.f + expf(-alpha[i]));
    float qm = 1.f - p * (1.f / (1.f + expf(-delta[i])));
    float th = 1.f / (1.f + expf(-theta[d]));
    float ph = th * (2.f * 3.14159265358979323846f * (float)(n + 1) / (float)EN);
    float c = cosf(ph), s = sinf(ph);
    g_coef[0][i] = qm * c;           // qr
    g_coef[1][i] = qm * s;           // qi
    g_coef[2][i] = p * c;            // ur
    g_coef[3][i] = p * s;            // ui
    g_coef[4][i] = gamma[i * 2 + 0]; // gr
    g_coef[5][i] = gamma[i * 2 + 1]; // gi
}

// ==================================================================
// CEMA scan: 8 lanes (n-states) per (b,d) channel; octet shfl reduce
// ==================================================================
__global__ void cema_scan(const float* __restrict__ omega) {
    int gt = blockIdx.x * blockDim.x + threadIdx.x;
    int unit = gt >> 3;
    int n = gt & 7;
    if (unit >= Bb * Dd) return;
    int b = unit / Dd, d = unit % Dd;
    int ci = d * EN + n;
    float qr = g_coef[0][ci], qi = g_coef[1][ci];
    float ur = g_coef[2][ci], ui = g_coef[3][ci];
    float gr = g_coef[4][ci], gi = g_coef[5][ci];
    float om = omega[d];
    float hr = 0.f, hi = 0.f;
    const float* xp = g_tsn + (size_t)b * Ss * Dd + d;
    float* op = g_cema + (size_t)b * Ss * Dd + d;
    for (int t = 0; t < Ss; t++) {
        float xv = xp[(size_t)t * Dd];
        float nhr = fmaf(qr, hr, fmaf(-qi, hi, ur * xv));
        float nhi = fmaf(qi, hr, fmaf(qr, hi, ui * xv));
        hr = nhr; hi = nhi;
        float y = nhr * gr + nhi * gi;
        y += __shfl_xor_sync(FULLMASK, y, 1);
        y += __shfl_xor_sync(FULLMASK, y, 2);
        y += __shfl_xor_sync(FULLMASK, y, 4);
        if (n == 0) op[(size_t)t * Dd] = fmaf(xv, om, y);
    }
}

// ==================================================================
// RMSNorm over D (mx = rmsnorm(cema) * rms_weight), one block per row
// ==================================================================
__global__ void rms_mx(const float* __restrict__ w) {
    int row = blockIdx.x;
    int t = threadIdx.x;
    const float* xr = g_cema + (size_t)row * Dd;
    float4 xv[2];
    float ss = 0.f;
    #pragma unroll
    for (int i = 0; i < 2; i++) {
        xv[i] = *(const float4*)(xr + (t + i * 256) * 4);
        ss += xv[i].x * xv[i].x + xv[i].y * xv[i].y + xv[i].z * xv[i].z + xv[i].w * xv[i].w;
    }
    __shared__ float sh[32];
    int lane = t & 31, wp = t >> 5;
    #pragma unroll
    for (int o = 16; o; o >>= 1) ss += __shfl_xor_sync(FULLMASK, ss, o);
    if (lane == 0) sh[wp] = ss;
    __syncthreads();
    if (wp == 0) {
        float v = (lane < 8) ? sh[lane] : 0.f;
        #pragma unroll
        for (int o = 16; o; o >>= 1) v += __shfl_xor_sync(FULLMASK, v, o);
        if (lane == 0) sh[0] = v;
    }
    __syncthreads();
    float inv = rsqrtf(sh[0] / (float)Dd + EPSC);
    float* orow = g_mx + (size_t)row * Dd;
    #pragma unroll
    for (int i = 0; i < 2; i++) {
        int c = (t + i * 256) * 4;
        float4 wv = *(const float4*)(w + c);
        float4 o;
        o.x = xv[i].x * inv * wv.x;
        o.y = xv[i].y * inv * wv.y;
        o.z = xv[i].z * inv * wv.z;
        o.w = xv[i].w * inv * wv.w;
        *(float4*)(orow + c) = o;
    }
}

// ==================================================================
// Generic fp32 SGEMM: C[M,N] = A[M,K] @ B[K,N]  (+bias +resid +silu +acc)
// 128x128x16 tile, 256 threads, 8x8 per thread
// ==================================================================
template <bool SILU, bool ACC, bool RESID, bool BIAS>
__global__ void __launch_bounds__(256) sgemm128(
    const float* __restrict__ A, const float* __restrict__ Bm,
    const float* __restrict__ bias, const float* __restrict__ resid,
    float* __restrict__ C, int M, int N, int K) {
    __shared__ float As[16][128];
    __shared__ float Bs[16][128];
    int bx = blockIdx.x, by = blockIdx.y;
    int tid = threadIdx.x;
    int arow = tid >> 2;
    int acol = (tid & 3) * 4;
    int brow = tid >> 5;
    int bcol = (tid & 31) * 4;
    int tm = (tid >> 4) * 8;
    int tn = (tid & 15) * 8;
    float acc[8][8];
    #pragma unroll
    for (int i = 0; i < 8; i++)
        #pragma unroll
        for (int j = 0; j < 8; j++) acc[i][j] = 0.f;

    const float* Aptr = A + (size_t)(by * 128) * K;
    const float* Bptr = Bm + bx * 128;

    for (int k0 = 0; k0 < K; k0 += 16) {
        #pragma unroll
        for (int i = 0; i < 2; i++) {
            int r = arow + i * 64;
            float4 v = *(const float4*)(Aptr + (size_t)r * K + k0 + acol);
            As[acol + 0][r] = v.x; As[acol + 1][r] = v.y;
            As[acol + 2][r] = v.z; As[acol + 3][r] = v.w;
        }
        #pragma unroll
        for (int i = 0; i < 2; i++) {
            int r = brow + i * 8;
            *(float4*)(&Bs[r][bcol]) = *(const float4*)(Bptr + (size_t)(k0 + r) * N + bcol);
        }
        __syncthreads();
        #pragma unroll
        for (int kk = 0; kk < 16; kk++) {
            float a[8], b[8];
            #pragma unroll
            for (int i = 0; i < 8; i++) a[i] = As[kk][tm + i];
            #pragma unroll
            for (int j = 0; j < 8; j++) b[j] = Bs[kk][tn + j];
            #pragma unroll
            for (int i = 0; i < 8; i++)
                #pragma unroll
                for (int j = 0; j < 8; j++) acc[i][j] = fmaf(a[i], b[j], acc[i][j]);
        }
        __syncthreads();
    }

    int crow0 = by * 128 + tm;
    int ccol0 = bx * 128 + tn;
    #pragma unroll
    for (int i = 0; i < 8; i++) {
        size_t roff = (size_t)(crow0 + i) * N + ccol0;
        #pragma unroll
        for (int jj = 0; jj < 2; jj++) {
            float4 o;
            float v[4];
            #pragma unroll
            for (int j = 0; j < 4; j++) {
                float c = acc[i][jj * 4 + j];
                if (BIAS)  c += bias[ccol0 + jj * 4 + j];
                if (RESID) c += resid[roff + jj * 4 + j];
                if (SILU)  c = c * sigmoidf_(c);
                if (ACC)   c += C[roff + jj * 4 + j];
                v[j] = c;
            }
            o.x = v[0]; o.y = v[1]; o.z = v[2]; o.w = v[3];
            *(float4*)(C + roff + jj * 4) = o;
        }
    }
}

// ==================================================================
// z head-RMS + gamma/beta + rotary -> q,k in (B,H,S,ZH) layout
// one block per (b,s); one warp per head; one lane per rotary pair
// ==================================================================
__global__ void qk_prep(const float* __restrict__ freqs, const float* __restrict__ agam,
                        const float* __restrict__ abeta) {
    int bs = blockIdx.x;
    int h = threadIdx.x >> 5, lane = threadIdx.x & 31;
    int b = bs / Ss, s = bs % Ss;
    const float* zr = g_z + (size_t)bs * Zz + h * ZH;
    float z0 = zr[2 * lane], z1 = zr[2 * lane + 1];
    float ss = z0 * z0 + z1 * z1;
    #pragma unroll
    for (int o = 16; o; o >>= 1) ss += __shfl_xor_sync(FULLMASK, ss, o);
    float inv = rsqrtf(ss / (float)ZH + EPSC);
    z0 *= inv; z1 *= inv;
    int j = h * ZH + 2 * lane;
    const float c0 = 0.125f;  // 1/sqrt(ZH)
    float gq0 = (agam[j] + 1.f) * c0,      gq1 = (agam[j + 1] + 1.f) * c0;
    float gk0 = (agam[Zz + j] + 1.f) * c0, gk1 = (agam[Zz + j + 1] + 1.f) * c0;
    float q0 = z0 * gq0 + abeta[j],        q1 = z1 * gq1 + abeta[j + 1];
    float k0 = z0 * gk0 + abeta[Zz + j],   k1 = z1 * gk1 + abeta[Zz + j + 1];
    float cv = freqs[(s * 32 + lane) * 2 + 0];
    float sv = freqs[(s * 32 + lane) * 2 + 1];
    float qa = q0 * cv - q1 * sv, qb = q0 * sv + q1 * cv;
    float ka = k0 * cv - k1 * sv, kb = k0 * sv + k1 * cv;
    float* qo = g_q + ((size_t)(b * Hh + h) * Ss + s) * ZH + 2 * lane;
    float* ko = g_k + ((size_t)(b * Hh + h) * Ss + s) * ZH + 2 * lane;
    qo[0] = qa; qo[1] = qb;
    ko[0] = ka; ko[1] = kb;
}

// ==================================================================
// Attention scores: 64x64 tile of Q @ K^T per block (causal tiles only)
// ==================================================================
__global__ void __launch_bounds__(256) attn_scores() {
    int kt = blockIdx.x, qt = blockIdx.y, bh = blockIdx.z;
    if (kt > qt) return;
    __shared__ float qs[64][65];
    __shared__ float ks[64][65];
    int tid = threadIdx.x;
    const float* qp = g_q + ((size_t)bh * Ss + qt * 64) * ZH;
    const float* kp = g_k + ((size_t)bh * Ss + kt * 64) * ZH;
    #pragma unroll
    for (int it = 0; it < 4; it++) {
        int f = it * 256 + tid;
        int r = f >> 4, c = (f & 15) * 4;
        float4 qv = *(const float4*)(qp + r * 64 + c);
        qs[r][c] = qv.x; qs[r][c + 1] = qv.y; qs[r][c + 2] = qv.z; qs[r][c + 3] = qv.w;
        float4 kv = *(const float4*)(kp + r * 64 + c);
        ks[r][c] = kv.x; ks[r][c + 1] = kv.y; ks[r][c + 2] = kv.z; ks[r][c + 3] = kv.w;
    }
    __syncthreads();
    int ty = tid >> 4, tx = tid & 15;
    int i0 = ty * 4, j0 = tx * 4;
    float acc[4][4];
    #pragma unroll
    for (int i = 0; i < 4; i++)
        #pragma unroll
        for (int j = 0; j < 4; j++) acc[i][j] = 0.f;
    #pragma unroll 8
    for (int d = 0; d < 64; d++) {
        float a[4], b[4];
        #pragma unroll
        for (int r = 0; r < 4; r++) a[r] = qs[i0 + r][d];
        #pragma unroll
        for (int c = 0; c < 4; c++) b[c] = ks[j0 + c][d];
        #pragma unroll
        for (int r = 0; r < 4; r++)
            #pragma unroll
            for (int c = 0; c < 4; c++) acc[r][c] = fmaf(a[r], b[c], acc[r][c]);
    }
    #pragma unroll
    for (int r = 0; r < 4; r++) {
        float4 o; o.x = acc[r][0]; o.y = acc[r][1]; o.z = acc[r][2]; o.w = acc[r][3];
        *(float4*)(g_scores + ((size_t)bh * Ss + qt * 64 + i0 + r) * Ss + kt * 64 + j0) = o;
    }
}

// ==================================================================
// Row softmax (causal), probs written in place; zero-fill to tile edge
// ==================================================================
__global__ void __launch_bounds__(256) attn_softmax() {
    int q = blockIdx.x, bh = blockIdx.y;
    float* row = g_scores + ((size_t)bh * Ss + q) * Ss;
    int klim = ((q >> 6) + 1) << 6;
    int t = threadIdx.x;
    int nc = (klim + 255) >> 8;
    float v[8];
    float m = -1e30f;
    for (int c = 0; c < nc; c++) {
        int idx = t + c * 256;
        v[c] = (idx <= q) ? row[idx] : -1e30f;
        m = fmaxf(m, v[c]);
    }
    __shared__ float sh[32];
    int lane = t & 31, wp = t >> 5;
    #pragma unroll
    for (int o = 16; o; o >>= 1) m = fmaxf(m, __shfl_xor_sync(FULLMASK, m, o));
    if (lane == 0) sh[wp] = m;
    __syncthreads();
    if (wp == 0) {
        float x = (lane < 8) ? sh[lane] : -1e30f;
        #pragma unroll
        for (int o = 16; o; o >>= 1) x = fmaxf(x, __shfl_xor_sync(FULLMASK, x, o));
        if (lane == 0) sh[0] = x;
    }
    __syncthreads();
    m = sh[0];
    __syncthreads();
    float sum = 0.f;
    for (int c = 0; c < nc; c++) {
        float e = __expf(v[c] - m);  // masked lanes underflow to 0
        v[c] = e;
        sum += e;
    }
    #pragma unroll
    for (int o = 16; o; o >>= 1) sum += __shfl_xor_sync(FULLMASK, sum, o);
    if (lane == 0) sh[wp] = sum;
    __syncthreads();
    if (wp == 0) {
        float x = (lane < 8) ? sh[lane] : 0.f;
        #pragma unroll
        for (int o = 16; o; o >>= 1) x += __shfl_xor_sync(FULLMASK, x, o);
        if (lane == 0) sh[0] = x;
    }
    __syncthreads();
    float inv = 1.f / sh[0];
    for (int c = 0; c < nc; c++) {
        int idx = t + c * 256;
        if (idx < klim) row[idx] = (idx <= q) ? v[c] * inv : 0.f;
    }
}

// ==================================================================
// attn = (P @ V) * r, 64x64 output tile per block (causal K loop)
// ==================================================================
__global__ void __launch_bounds__(256) attn_pv(const float* __restrict__ rgate) {
    int nt = blockIdx.x, qt = blockIdx.y, bh = blockIdx.z;
    int b = bh >> 3, h = bh & 7;
    __shared__ float ps[64][65];
    __shared__ float vs[64][65];
    int tid = threadIdx.x;
    int ty = tid >> 4, tx = tid & 15;
    int i0 = ty * 4, j0 = tx * 4;
    float acc[4][4];
    #pragma unroll
    for (int i = 0; i < 4; i++)
        #pragma unroll
        for (int j = 0; j < 4; j++) acc[i][j] = 0.f;

    const float* pbase = g_scores + ((size_t)bh * Ss + qt * 64) * Ss;
    const float* vbase = g_v + (size_t)b * Ss * HDim + h * VH + nt * 64;

    for (int kt = 0; kt <= qt; kt++) {
        #pragma unroll
        for (int it = 0; it < 4; it++) {
            int f = it * 256 + tid;
            int r = f >> 4, c = (f & 15) * 4;
            float4 p4 = *(const float4*)(pbase + (size_t)r * Ss + kt * 64 + c);
            ps[r][c] = p4.x; ps[r][c + 1] = p4.y; ps[r][c + 2] = p4.z; ps[r][c + 3] = p4.w;
            float4 v4 = *(const float4*)(vbase + (size_t)(kt * 64 + r) * HDim + c);
            vs[r][c] = v4.x; vs[r][c + 1] = v4.y; vs[r][c + 2] = v4.z; vs[r][c + 3] = v4.w;
        }
        __syncthreads();
        #pragma unroll 8
        for (int kk = 0; kk < 64; kk++) {
            float a[4], b2[4];
            #pragma unroll
            for (int r = 0; r < 4; r++) a[r] = ps[i0 + r][kk];
            #pragma unroll
            for (int c = 0; c < 4; c++) b2[c] = vs[kk][j0 + c];
            #pragma unroll
            for (int r = 0; r < 4; r++)
                #pragma unroll
                for (int c = 0; c < 4; c++) acc[r][c] = fmaf(a[r], b2[c], acc[r][c]);
        }
        __syncthreads();
    }
    #pragma unroll
    for (int r = 0; r < 4; r++) {
        int qg = qt * 64 + i0 + r;
        size_t o = ((size_t)b * Ss + qg) * HDim + h * VH + nt * 64 + j0;
        float4 rg = *(const float4*)(rgate + o);
        float4 ov;
        ov.x = acc[r][0] * rg.x; ov.y = acc[r][1] * rg.y;
        ov.z = acc[r][2] * rg.z; ov.w = acc[r][3] * rg.w;
        *(float4*)(g_attn + o) = ov;
    }
}

// ==================================================================
// launch
// ==================================================================
extern "C" void kernel_launch(void* const* d_in, const int* in_sizes, int n_in,
                              void* d_out, int out_size) {
    const float *x, *freqs, *tn_w, *tn_b, *alpha, *delta, *theta, *gamma, *omega, *rms_w;
    const float *wz_w, *wz_b, *wv_w, *wv_b, *wr_w, *wr_b, *wh1_w, *wh1_b, *wh2_w, *agam, *abeta;

    if (in_sizes[1] == Ss * 32 * 2) {
        // reference signature order: x, freqs_cis, ...
        x = (const float*)d_in[0];  freqs = (const float*)d_in[1];
        tn_w = (const float*)d_in[2]; tn_b = (const float*)d_in[3];
        alpha = (const float*)d_in[4]; delta = (const float*)d_in[5];
        theta = (const float*)d_in[6]; gamma = (const float*)d_in[7];
        omega = (const float*)d_in[8]; rms_w = (const float*)d_in[9];
        wz_w = (const float*)d_in[10]; wz_b = (const float*)d_in[11];
        wv_w = (const float*)d_in[12]; wv_b = (const float*)d_in[13];
        wr_w = (const float*)d_in[14]; wr_b = (const float*)d_in[15];
        wh1_w = (const float*)d_in[16]; wh1_b = (const float*)d_in[17];
        wh2_w = (const float*)d_in[18];
        agam = (const float*)d_in[19]; abeta = (const float*)d_in[20];
    } else {
        // setup_inputs dict-insertion order: freqs_cis last
        x = (const float*)d_in[0];
        tn_w = (const float*)d_in[1]; tn_b = (const float*)d_in[2];
        alpha = (const float*)d_in[3]; delta = (const float*)d_in[4];
        theta = (const float*)d_in[5]; gamma = (const float*)d_in[6];
        omega = (const float*)d_in[7]; rms_w = (const float*)d_in[8];
        wz_w = (const float*)d_in[9]; wz_b = (const float*)d_in[10];
        wv_w = (const float*)d_in[11]; wv_b = (const float*)d_in[12];
        wr_w = (const float*)d_in[13]; wr_b = (const float*)d_in[14];
        wh1_w = (const float*)d_in[15]; wh1_b = (const float*)d_in[16];
        wh2_w = (const float*)d_in[17];
        agam = (const float*)d_in[18]; abeta = (const float*)d_in[19];
        freqs = (const float*)d_in[20];
    }

    float* out = (float*)d_out;
    const int M = Bb * Ss;  // 4096

    // scratch pointers for sgemm A/C
    float *p_tsn, *p_mx, *p_z, *p_v, *p_r, *p_attn;
    cudaGetSymbolAddress((void**)&p_tsn, g_tsn);
    cudaGetSymbolAddress((void**)&p_mx, g_mx);
    cudaGetSymbolAddress((void**)&p_z, g_z);
    cudaGetSymbolAddress((void**)&p_v, g_v);
    cudaGetSymbolAddress((void**)&p_r, g_r);
    cudaGetSymbolAddress((void**)&p_attn, g_attn);

    // 1-3: timestep norm
    tsn_partial<<<(Bb * Ss * Gg) / 8, 256>>>(x);
    tsn_scan<<<Bb * Gg, 256>>>();
    tsn_norm<<<(Bb * Ss * Dd / 4) / 256, 256>>>(x, tn_w, tn_b);

    // 4-5: cema
    cema_coef<<<(Dd * EN) / 256, 256>>>(alpha, delta, theta, gamma);
    cema_scan<<<(Bb * Dd * 8) / 256, 256>>>(omega);

    // 6: mx = rmsnorm(cema)*w
    rms_mx<<<M, 256>>>(rms_w);

    // 7: z = mx @ wz_w + wz_b
    sgemm128<false, false, false, true><<<dim3(Zz / 128, M / 128), 256>>>(
        p_mx, wz_w, wz_b, nullptr, p_z, M, Zz, Dd);

    // 8: head-RMS + gamma/beta + rotary
    qk_prep<<<M, 256>>>(freqs, agam, abeta);

    // 9-10: v = silu(tsn @ wv + b), r = silu(mx @ wr + b)
    sgemm128<true, false, false, true><<<dim3(HDim / 128, M / 128), 256>>>(
        p_tsn, wv_w, wv_b, nullptr, p_v, M, HDim, Dd);
    sgemm128<true, false, false, true><<<dim3(HDim / 128, M / 128), 256>>>(
        p_mx, wr_w, wr_b, nullptr, p_r, M, HDim, Dd);

    // 11-13: attention
    attn_scores<<<dim3(Ss / 64, Ss / 64, BHh), 256>>>();
    attn_softmax<<<dim3(Ss, BHh), 256>>>();
    attn_pv<<<dim3(VH / 64, Ss / 64, BHh), 256>>>(p_r);

    // 14: out = mx @ wh1 + wh1_b + x
    sgemm128<false, false, true, true><<<dim3(Dd / 128, M / 128), 256>>>(
        p_mx, wh1_w, wh1_b, x, out, M, Dd, Dd);
    // 15: out += attn @ wh2
    sgemm128<false, true, false, false><<<dim3(Dd / 128, M / 128), 256>>>(
        p_attn, wh2_w, nullptr, nullptr, out, M, Dd, HDim);
}

// round 3
// speedup vs baseline: 1.3599x; 1.3599x over previous
#include <cuda_runtime.h>
#include <cuda_bf16.h>
#include <mma.h>
#include <math.h>
#include <stdint.h>

using namespace nvcuda;

#define FULLMASK 0xffffffffu

// ---------------- problem constants ----------------
constexpr int Bb = 2, Ss = 2048, Dd = 2048;
constexpr int Zz = 512, HDim = 4096, Hh = 8, EN = 8;
constexpr int ZH = 64, VH = 512;
constexpr int Gg = 32, DG = 64;
constexpr int BHh = Bb * Hh;
constexpr float EPSC = 1e-5f;

// ---------------- scratch (device globals; no allocation allowed) ----------------
__device__ float g_tsn [Bb * Ss * Dd];
__device__ float g_cema[Bb * Ss * Dd];
__device__ float g_mx  [Bb * Ss * Dd];
__device__ float g_z   [Bb * Ss * Zz];
__device__ float g_q   [BHh * Ss * ZH];
__device__ float g_k   [BHh * Ss * ZH];
__device__ float g_v   [Bb * Ss * HDim];
__device__ float g_r   [Bb * Ss * HDim];
__device__ float g_attn[Bb * Ss * HDim];
__device__ float g_scores[(size_t)BHh * Ss * Ss];
__device__ float g_p1[Bb * Gg * Ss];
__device__ float g_p2[Bb * Gg * Ss];
__device__ float g_c1[Bb * Gg * Ss];
__device__ float g_c2[Bb * Gg * Ss];
__device__ float g_coef[6][Dd * EN];

// ---------------- helpers ----------------
__device__ __forceinline__ float sigmoidf_(float x) { return 1.f / (1.f + __expf(-x)); }

// ==================================================================
// WMMA bf16 3-product GEMM: C[M,N] = A[M,K] @ W[K,N] (+bias+resid+silu+acc)
// 128x128x32 tile, 256 threads, 8 warps (4x2), warp tile 32x64
// ==================================================================
constexpr int ALD = 40;    // A smem leading dim (bf16)
constexpr int BLD = 136;   // B smem leading dim (bf16)
constexpr int CLD = 132;   // C epilogue smem leading dim (float)
constexpr int OFF_AH = 0;
constexpr int OFF_AL = OFF_AH + 128 * ALD * 2;             // 10240
constexpr int OFF_BH = OFF_AL + 128 * ALD * 2;             // 20480
constexpr int OFF_BL = OFF_BH + 32 * BLD * 2;              // 29184
constexpr int MM_SMEM = 128 * CLD * 4;                     // 67584 (union, epilogue)

template <bool SILU, bool ACC, bool RESID, bool BIAS>
__global__ void __launch_bounds__(256) mma_gemm(
    const float* __restrict__ A, const float* __restrict__ W,
    const float* __restrict__ bias, const float* __restrict__ resid,
    float* __restrict__ C, int M, int N, int K) {
    extern __shared__ char sm[];
    __nv_bfloat16* Ah = (__nv_bfloat16*)(sm + OFF_AH);
    __nv_bfloat16* Al = (__nv_bfloat16*)(sm + OFF_AL);
    __nv_bfloat16* Bh = (__nv_bfloat16*)(sm + OFF_BH);
    __nv_bfloat16* Bl = (__nv_bfloat16*)(sm + OFF_BL);
    float* Ct = (float*)sm;

    const int tid = threadIdx.x;
    const int wid = tid >> 5;
    const int m0 = blockIdx.y * 128;
    const int n0 = blockIdx.x * 128;
    const int wm = (wid & 3) * 32;     // warp row offset
    const int wn = (wid >> 2) * 64;    // warp col offset

    const int arow = tid >> 3, ac4 = tid & 7;    // A: 32 rows/pass x 8 float4
    const int brow = tid >> 5, bc4 = tid & 31;   // B: 8 rows/pass x 32 float4

    wmma::fragment<wmma::accumulator, 16, 16, 16, float> acc[2][4];
    #pragma unroll
    for (int r = 0; r < 2; r++)
        #pragma unroll
        for (int c = 0; c < 4; c++) wmma::fill_fragment(acc[r][c], 0.f);

    const int nk = K / 32;
    float4 ra[4], rb[4];

    // prefetch tile 0
    #pragma unroll
    for (int p = 0; p < 4; p++)
        ra[p] = *(const float4*)(A + (size_t)(m0 + arow + p * 32) * K + ac4 * 4);
    #pragma unroll
    for (int p = 0; p < 4; p++)
        rb[p] = *(const float4*)(W + (size_t)(brow + p * 8) * N + n0 + bc4 * 4);

    for (int it = 0; it < nk; it++) {
        // store prefetched regs -> smem as bf16 hi/lo
        #pragma unroll
        for (int p = 0; p < 4; p++) {
            float4 v = ra[p];
            __nv_bfloat162 h01 = __floats2bfloat162_rn(v.x, v.y);
            __nv_bfloat162 h23 = __floats2bfloat162_rn(v.z, v.w);
            __nv_bfloat162 l01 = __floats2bfloat162_rn(
                v.x - __bfloat162float(h01.x), v.y - __bfloat162float(h01.y));
            __nv_bfloat162 l23 = __floats2bfloat162_rn(
                v.z - __bfloat162float(h23.x), v.w - __bfloat162float(h23.y));
            int off = (arow + p * 32) * ALD + ac4 * 4;
            *(__nv_bfloat162*)(Ah + off) = h01;
            *(__nv_bfloat162*)(Ah + off + 2) = h23;
            *(__nv_bfloat162*)(Al + off) = l01;
            *(__nv_bfloat162*)(Al + off + 2) = l23;
        }
        #pragma unroll
        for (int p = 0; p < 4; p++) {
            float4 v = rb[p];
            __nv_bfloat162 h01 = __floats2bfloat162_rn(v.x, v.y);
            __nv_bfloat162 h23 = __floats2bfloat162_rn(v.z, v.w);
            __nv_bfloat162 l01 = __floats2bfloat162_rn(
                v.x - __bfloat162float(h01.x), v.y - __bfloat162float(h01.y));
            __nv_bfloat162 l23 = __floats2bfloat162_rn(
                v.z - __bfloat162float(h23.x), v.w - __bfloat162float(h23.y));
            int off = (brow + p * 8) * BLD + bc4 * 4;
            *(__nv_bfloat162*)(Bh + off) = h01;
            *(__nv_bfloat162*)(Bh + off + 2) = h23;
            *(__nv_bfloat162*)(Bl + off) = l01;
            *(__nv_bfloat162*)(Bl + off + 2) = l23;
        }
        __syncthreads();

        // prefetch next tile while MMAs run
        if (it + 1 < nk) {
            int k0 = (it + 1) * 32;
            #pragma unroll
            for (int p = 0; p < 4; p++)
                ra[p] = *(const float4*)(A + (size_t)(m0 + arow + p * 32) * K + k0 + ac4 * 4);
            #pragma unroll
            for (int p = 0; p < 4; p++)
                rb[p] = *(const float4*)(W + (size_t)(k0 + brow + p * 8) * N + n0 + bc4 * 4);
        }

        #pragma unroll
        for (int kk = 0; kk < 2; kk++) {
            wmma::fragment<wmma::matrix_a, 16, 16, 16, __nv_bfloat16, wmma::row_major> fah[2], fal[2];
            #pragma unroll
            for (int r = 0; r < 2; r++) {
                wmma::load_matrix_sync(fah[r], Ah + (wm + r * 16) * ALD + kk * 16, ALD);
                wmma::load_matrix_sync(fal[r], Al + (wm + r * 16) * ALD + kk * 16, ALD);
            }
            #pragma unroll
            for (int c = 0; c < 4; c++) {
                wmma::fragment<wmma::matrix_b, 16, 16, 16, __nv_bfloat16, wmma::row_major> fbh, fbl;
                wmma::load_matrix_sync(fbh, Bh + (kk * 16) * BLD + wn + c * 16, BLD);
                wmma::load_matrix_sync(fbl, Bl + (kk * 16) * BLD + wn + c * 16, BLD);
                #pragma unroll
                for (int r = 0; r < 2; r++) {
                    wmma::mma_sync(acc[r][c], fah[r], fbh, acc[r][c]);
                    wmma::mma_sync(acc[r][c], fah[r], fbl, acc[r][c]);
                    wmma::mma_sync(acc[r][c], fal[r], fbh, acc[r][c]);
                }
            }
        }
        __syncthreads();
    }

    // epilogue via smem
    #pragma unroll
    for (int r = 0; r < 2; r++)
        #pragma unroll
        for (int c = 0; c < 4; c++)
            wmma::store_matrix_sync(Ct + (wm + r * 16) * CLD + wn + c * 16,
                                    acc[r][c], CLD, wmma::mem_row_major);
    __syncthreads();

    #pragma unroll
    for (int i = 0; i < 16; i++) {
        int flat = i * 256 + tid;
        int row = flat >> 5, col4 = (flat & 31) * 4;
        size_t goff = (size_t)(m0 + row) * N + n0 + col4;
        float v[4];
        #pragma unroll
        for (int e = 0; e < 4; e++) {
            float cv = Ct[row * CLD + col4 + e];
            if (BIAS)  cv += bias[n0 + col4 + e];
            if (RESID) cv += resid[goff + e];
            if (SILU)  cv = cv * sigmoidf_(cv);
            if (ACC)   cv += C[goff + e];
            v[e] = cv;
        }
        float4 o; o.x = v[0]; o.y = v[1]; o.z = v[2]; o.w = v[3];
        *(float4*)(C + goff) = o;
    }
}

// ==================================================================
// Timestep norm: stage 1
// ==================================================================
__global__ void tsn_partial(const float* __restrict__ x) {
    int warp = (blockIdx.x * blockDim.x + threadIdx.x) >> 5;
    int lane = threadIdx.x & 31;
    if (warp >= Bb * Ss * Gg) return;
    int g = warp % Gg;
    int s = (warp / Gg) % Ss;
    int b = warp / (Gg * Ss);
    const float* p = x + ((size_t)(b * Ss + s)) * Dd + g * DG;
    float v0 = p[lane], v1 = p[lane + 32];
    float s1 = v0 + v1;
    float s2 = v0 * v0 + v1 * v1;
    #pragma unroll
    for (int o = 16; o; o >>= 1) {
        s1 += __shfl_down_sync(FULLMASK, s1, o);
        s2 += __shfl_down_sync(FULLMASK, s2, o);
    }
    if (lane == 0) {
        int idx = (b * Gg + g) * Ss + s;
        g_p1[idx] = s1;
        g_p2[idx] = s2;
    }
}

// ==================================================================
// Timestep norm: stage 2 — inclusive prefix scan over S per (b,g)
// ==================================================================
__global__ void tsn_scan() {
    int bg = blockIdx.x;
    int t  = threadIdx.x;
    const float* r1 = g_p1 + bg * Ss;
    const float* r2 = g_p2 + bg * Ss;
    float v1[8], v2[8];
    float a1 = 0.f, a2 = 0.f;
    #pragma unroll
    for (int i = 0; i < 8; i++) {
        a1 += r1[t * 8 + i]; v1[i] = a1;
        a2 += r2[t * 8 + i]; v2[i] = a2;
    }
    __shared__ float sh1[256], sh2[256];
    sh1[t] = a1; sh2[t] = a2;
    __syncthreads();
    for (int off = 1; off < 256; off <<= 1) {
        float b1 = 0.f, b2 = 0.f;
        if (t >= off) { b1 = sh1[t - off]; b2 = sh2[t - off]; }
        __syncthreads();
        sh1[t] += b1; sh2[t] += b2;
        __syncthreads();
    }
    float o1 = t ? sh1[t - 1] : 0.f;
    float o2 = t ? sh2[t - 1] : 0.f;
    float* w1 = g_c1 + bg * Ss;
    float* w2 = g_c2 + bg * Ss;
    #pragma unroll
    for (int i = 0; i < 8; i++) {
        w1[t * 8 + i] = v1[i] + o1;
        w2[t * 8 + i] = v2[i] + o2;
    }
}

// ==================================================================
// Timestep norm: stage 3 — elementwise normalize
// ==================================================================
__global__ void tsn_norm(const float* __restrict__ x, const float* __restrict__ w,
                         const float* __restrict__ bias) {
    int i4 = blockIdx.x * blockDim.x + threadIdx.x;
    if (i4 >= Bb * Ss * Dd / 4) return;
    int d4 = i4 % (Dd / 4);
    int s  = (i4 / (Dd / 4)) % Ss;
    int b  = i4 / (Dd / 4 * Ss);
    int d  = d4 * 4;
    int g  = d / DG;
    int ci = (b * Gg + g) * Ss + s;
    float cnt  = (float)(s + 1) * (float)DG;
    float mean = g_c1[ci] / cnt;
    float var  = g_c2[ci] / cnt - mean * mean;
    float inv  = rsqrtf(var + EPSC);
    float4 xv = *(const float4*)(x + (size_t)i4 * 4);
    float4 wv = *(const float4*)(w + d);
    float4 bv = *(const float4*)(bias + d);
    float4 o;
    o.x = (xv.x - mean) * inv * wv.x + bv.x;
    o.y = (xv.y - mean) * inv * wv.y + bv.y;
    o.z = (xv.z - mean) * inv * wv.z + bv.z;
    o.w = (xv.w - mean) * inv * wv.w + bv.w;
    *(float4*)(g_tsn + (size_t)i4 * 4) = o;
}

// ==================================================================
// CEMA coefficient precompute
// ==================================================================
__global__ void cema_coef(const float* __restrict__ alpha, const float* __restrict__ delta,
                          const float* __restrict__ theta, const float* __restrict__ gamma) {
    int i = blockIdx.x * blockDim.x + threadIdx.x;
    if (i >= Dd * EN) return;
    int d = i / EN, n = i % EN;
    float p  = 1.f / (1.f + expf(-alpha[i]));
    float qm = 1.f - p * (1.f / (1.f + expf(-delta[i])));
    float th = 1.f / (1.f + expf(-theta[d]));
    float ph = th * (2.f * 3.14159265358979323846f * (float)(n + 1) / (float)EN);
    float c = cosf(ph), s = sinf(ph);
    g_coef[0][i] = qm * c;
    g_coef[1][i] = qm * s;
    g_coef[2][i] = p * c;
    g_coef[3][i] = p * s;
    g_coef[4][i] = gamma[i * 2 + 0];
    g_coef[5][i] = gamma[i * 2 + 1];
}

// ==================================================================
// CEMA scan
// ==================================================================
__global__ void cema_scan(const float* __restrict__ omega) {
    int gt = blockIdx.x * blockDim.x + threadIdx.x;
    int unit = gt >> 3;
    int n = gt & 7;
    if (unit >= Bb * Dd) return;
    int b = unit / Dd, d = unit % Dd;
    int ci = d * EN + n;
    float qr = g_coef[0][ci], qi = g_coef[1][ci];
    float ur = g_coef[2][ci], ui = g_coef[3][ci];
    float gr = g_coef[4][ci], gi = g_coef[5][ci];
    float om = omega[d];
    float hr = 0.f, hi = 0.f;
    const float* xp = g_tsn + (size_t)b * Ss * Dd + d;
    float* op = g_cema + (size_t)b * Ss * Dd + d;
    for (int t = 0; t < Ss; t++) {
        float xv = xp[(size_t)t * Dd];
        float nhr = fmaf(qr, hr, fmaf(-qi, hi, ur * xv));
        float nhi = fmaf(qi, hr, fmaf(qr, hi, ui * xv));
        hr = nhr; hi = nhi;
        float y = nhr * gr + nhi * gi;
        y += __shfl_xor_sync(FULLMASK, y, 1);
        y += __shfl_xor_sync(FULLMASK, y, 2);
        y += __shfl_xor_sync(FULLMASK, y, 4);
        if (n == 0) op[(size_t)t * Dd] = fmaf(xv, om, y);
    }
}

// ==================================================================
// RMSNorm over D
// ==================================================================
__global__ void rms_mx(const float* __restrict__ w) {
    int row = blockIdx.x;
    int t = threadIdx.x;
    const float* xr = g_cema + (size_t)row * Dd;
    float4 xv[2];
    float ss = 0.f;
    #pragma unroll
    for (int i = 0; i < 2; i++) {
        xv[i] = *(const float4*)(xr + (t + i * 256) * 4);
        ss += xv[i].x * xv[i].x + xv[i].y * xv[i].y + xv[i].z * xv[i].z + xv[i].w * xv[i].w;
    }
    __shared__ float sh[32];
    int lane = t & 31, wp = t >> 5;
    #pragma unroll
    for (int o = 16; o; o >>= 1) ss += __shfl_xor_sync(FULLMASK, ss, o);
    if (lane == 0) sh[wp] = ss;
    __syncthreads();
    if (wp == 0) {
        float v = (lane < 8) ? sh[lane] : 0.f;
        #pragma unroll
        for (int o = 16; o; o >>= 1) v += __shfl_xor_sync(FULLMASK, v, o);
        if (lane == 0) sh[0] = v;
    }
    __syncthreads();
    float inv = rsqrtf(sh[0] / (float)Dd + EPSC);
    float* orow = g_mx + (size_t)row * Dd;
    #pragma unroll
    for (int i = 0; i < 2; i++) {
        int c = (t + i * 256) * 4;
        float4 wv = *(const float4*)(w + c);
        float4 o;
        o.x = xv[i].x * inv * wv.x;
        o.y = xv[i].y * inv * wv.y;
        o.z = xv[i].z * inv * wv.z;
        o.w = xv[i].w * inv * wv.w;
        *(float4*)(orow + c) = o;
    }
}

// ==================================================================
// z head-RMS + gamma/beta + rotary -> q,k in (B,H,S,ZH) layout
// ==================================================================
__global__ void qk_prep(const float* __restrict__ freqs, const float* __restrict__ agam,
                        const float* __restrict__ abeta) {
    int bs = blockIdx.x;
    int h = threadIdx.x >> 5, lane = threadIdx.x & 31;
    int b = bs / Ss, s = bs % Ss;
    const float* zr = g_z + (size_t)bs * Zz + h * ZH;
    float z0 = zr[2 * lane], z1 = zr[2 * lane + 1];
    float ss = z0 * z0 + z1 * z1;
    #pragma unroll
    for (int o = 16; o; o >>= 1) ss += __shfl_xor_sync(FULLMASK, ss, o);
    float inv = rsqrtf(ss / (float)ZH + EPSC);
    z0 *= inv; z1 *= inv;
    int j = h * ZH + 2 * lane;
    const float c0 = 0.125f;
    float gq0 = (agam[j] + 1.f) * c0,      gq1 = (agam[j + 1] + 1.f) * c0;
    float gk0 = (agam[Zz + j] + 1.f) * c0, gk1 = (agam[Zz + j + 1] + 1.f) * c0;
    float q0 = z0 * gq0 + abeta[j],        q1 = z1 * gq1 + abeta[j + 1];
    float k0 = z0 * gk0 + abeta[Zz + j],   k1 = z1 * gk1 + abeta[Zz + j + 1];
    float cv = freqs[(s * 32 + lane) * 2 + 0];
    float sv = freqs[(s * 32 + lane) * 2 + 1];
    float qa = q0 * cv - q1 * sv, qb = q0 * sv + q1 * cv;
    float ka = k0 * cv - k1 * sv, kb = k0 * sv + k1 * cv;
    float* qo = g_q + ((size_t)(b * Hh + h) * Ss + s) * ZH + 2 * lane;
    float* ko = g_k + ((size_t)(b * Hh + h) * Ss + s) * ZH + 2 * lane;
    qo[0] = qa; qo[1] = qb;
    ko[0] = ka; ko[1] = kb;
}

// ==================================================================
// Attention scores: 64x64 tile (causal tiles only)
// ==================================================================
__global__ void __launch_bounds__(256) attn_scores() {
    int kt = blockIdx.x, qt = blockIdx.y, bh = blockIdx.z;
    if (kt > qt) return;
    __shared__ float qs[64][65];
    __shared__ float ks[64][65];
    int tid = threadIdx.x;
    const float* qp = g_q + ((size_t)bh * Ss + qt * 64) * ZH;
    const float* kp = g_k + ((size_t)bh * Ss + kt * 64) * ZH;
    #pragma unroll
    for (int it = 0; it < 4; it++) {
        int f = it * 256 + tid;
        int r = f >> 4, c = (f & 15) * 4;
        float4 qv = *(const float4*)(qp + r * 64 + c);
        qs[r][c] = qv.x; qs[r][c + 1] = qv.y; qs[r][c + 2] = qv.z; qs[r][c + 3] = qv.w;
        float4 kv = *(const float4*)(kp + r * 64 + c);
        ks[r][c] = kv.x; ks[r][c + 1] = kv.y; ks[r][c + 2] = kv.z; ks[r][c + 3] = kv.w;
    }
    __syncthreads();
    int ty = tid >> 4, tx = tid & 15;
    int i0 = ty * 4, j0 = tx * 4;
    float acc[4][4];
    #pragma unroll
    for (int i = 0; i < 4; i++)
        #pragma unroll
        for (int j = 0; j < 4; j++) acc[i][j] = 0.f;
    #pragma unroll 8
    for (int d = 0; d < 64; d++) {
        float a[4], b[4];
        #pragma unroll
        for (int r = 0; r < 4; r++) a[r] = qs[i0 + r][d];
        #pragma unroll
        for (int c = 0; c < 4; c++) b[c] = ks[j0 + c][d];
        #pragma unroll
        for (int r = 0; r < 4; r++)
            #pragma unroll
            for (int c = 0; c < 4; c++) acc[r][c] = fmaf(a[r], b[c], acc[r][c]);
    }
    #pragma unroll
    for (int r = 0; r < 4; r++) {
        float4 o; o.x = acc[r][0]; o.y = acc[r][1]; o.z = acc[r][2]; o.w = acc[r][3];
        *(float4*)(g_scores + ((size_t)bh * Ss + qt * 64 + i0 + r) * Ss + kt * 64 + j0) = o;
    }
}

// ==================================================================
// Row softmax (causal)
// ==================================================================
__global__ void __launch_bounds__(256) attn_softmax() {
    int q = blockIdx.x, bh = blockIdx.y;
    float* row = g_scores + ((size_t)bh * Ss + q) * Ss;
    int klim = ((q >> 6) + 1) << 6;
    int t = threadIdx.x;
    int nc = (klim + 255) >> 8;
    float v[8];
    float m = -1e30f;
    for (int c = 0; c < nc; c++) {
        int idx = t + c * 256;
        v[c] = (idx <= q) ? row[idx] : -1e30f;
        m = fmaxf(m, v[c]);
    }
    __shared__ float sh[32];
    int lane = t & 31, wp = t >> 5;
    #pragma unroll
    for (int o = 16; o; o >>= 1) m = fmaxf(m, __shfl_xor_sync(FULLMASK, m, o));
    if (lane == 0) sh[wp] = m;
    __syncthreads();
    if (wp == 0) {
        float x = (lane < 8) ? sh[lane] : -1e30f;
        #pragma unroll
        for (int o = 16; o; o >>= 1) x = fmaxf(x, __shfl_xor_sync(FULLMASK, x, o));
        if (lane == 0) sh[0] = x;
    }
    __syncthreads();
    m = sh[0];
    __syncthreads();
    float sum = 0.f;
    for (int c = 0; c < nc; c++) {
        float e = __expf(v[c] - m);
        v[c] = e;
        sum += e;
    }
    #pragma unroll
    for (int o = 16; o; o >>= 1) sum += __shfl_xor_sync(FULLMASK, sum, o);
    if (lane == 0) sh[wp] = sum;
    __syncthreads();
    if (wp == 0) {
        float x = (lane < 8) ? sh[lane] : 0.f;
        #pragma unroll
        for (int o = 16; o; o >>= 1) x += __shfl_xor_sync(FULLMASK, x, o);
        if (lane == 0) sh[0] = x;
    }
    __syncthreads();
    float inv = 1.f / sh[0];
    for (int c = 0; c < nc; c++) {
        int idx = t + c * 256;
        if (idx < klim) row[idx] = (idx <= q) ? v[c] * inv : 0.f;
    }
}

// ==================================================================
// attn = (P @ V) * r
// ==================================================================
__global__ void __launch_bounds__(256) attn_pv(const float* __restrict__ rgate) {
    int nt = blockIdx.x, qt = blockIdx.y, bh = blockIdx.z;
    int b = bh >> 3, h = bh & 7;
    __shared__ float ps[64][65];
    __shared__ float vs[64][65];
    int tid = threadIdx.x;
    int ty = tid >> 4, tx = tid & 15;
    int i0 = ty * 4, j0 = tx * 4;
    float acc[4][4];
    #pragma unroll
    for (int i = 0; i < 4; i++)
        #pragma unroll
        for (int j = 0; j < 4; j++) acc[i][j] = 0.f;

    const float* pbase = g_scores + ((size_t)bh * Ss + qt * 64) * Ss;
    const float* vbase = g_v + (size_t)b * Ss * HDim + h * VH + nt * 64;

    for (int kt = 0; kt <= qt; kt++) {
        #pragma unroll
        for (int it = 0; it < 4; it++) {
            int f = it * 256 + tid;
            int r = f >> 4, c = (f & 15) * 4;
            float4 p4 = *(const float4*)(pbase + (size_t)r * Ss + kt * 64 + c);
            ps[r][c] = p4.x; ps[r][c + 1] = p4.y; ps[r][c + 2] = p4.z; ps[r][c + 3] = p4.w;
            float4 v4 = *(const float4*)(vbase + (size_t)(kt * 64 + r) * HDim + c);
            vs[r][c] = v4.x; vs[r][c + 1] = v4.y; vs[r][c + 2] = v4.z; vs[r][c + 3] = v4.w;
        }
        __syncthreads();
        #pragma unroll 8
        for (int kk = 0; kk < 64; kk++) {
            float a[4], b2[4];
            #pragma unroll
            for (int r = 0; r < 4; r++) a[r] = ps[i0 + r][kk];
            #pragma unroll
            for (int c = 0; c < 4; c++) b2[c] = vs[kk][j0 + c];
            #pragma unroll
            for (int r = 0; r < 4; r++)
                #pragma unroll
                for (int c = 0; c < 4; c++) acc[r][c] = fmaf(a[r], b2[c], acc[r][c]);
        }
        __syncthreads();
    }
    #pragma unroll
    for (int r = 0; r < 4; r++) {
        int qg = qt * 64 + i0 + r;
        size_t o = ((size_t)b * Ss + qg) * HDim + h * VH + nt * 64 + j0;
        float4 rg = *(const float4*)(rgate + o);
        float4 ov;
        ov.x = acc[r][0] * rg.x; ov.y = acc[r][1] * rg.y;
        ov.z = acc[r][2] * rg.z; ov.w = acc[r][3] * rg.w;
        *(float4*)(g_attn + o) = ov;
    }
}

// ==================================================================
// launch
// ==================================================================
extern "C" void kernel_launch(void* const* d_in, const int* in_sizes, int n_in,
                              void* d_out, int out_size) {
    const float *x, *freqs, *tn_w, *tn_b, *alpha, *delta, *theta, *gamma, *omega, *rms_w;
    const float *wz_w, *wz_b, *wv_w, *wv_b, *wr_w, *wr_b, *wh1_w, *wh1_b, *wh2_w, *agam, *abeta;

    if (in_sizes[1] == Ss * 32 * 2) {
        x = (const float*)d_in[0];  freqs = (const float*)d_in[1];
        tn_w = (const float*)d_in[2]; tn_b = (const float*)d_in[3];
        alpha = (const float*)d_in[4]; delta = (const float*)d_in[5];
        theta = (const float*)d_in[6]; gamma = (const float*)d_in[7];
        omega = (const float*)d_in[8]; rms_w = (const float*)d_in[9];
        wz_w = (const float*)d_in[10]; wz_b = (const float*)d_in[11];
        wv_w = (const float*)d_in[12]; wv_b = (const float*)d_in[13];
        wr_w = (const float*)d_in[14]; wr_b = (const float*)d_in[15];
        wh1_w = (const float*)d_in[16]; wh1_b = (const float*)d_in[17];
        wh2_w = (const float*)d_in[18];
        agam = (const float*)d_in[19]; abeta = (const float*)d_in[20];
    } else {
        x = (const float*)d_in[0];
        tn_w = (const float*)d_in[1]; tn_b = (const float*)d_in[2];
        alpha = (const float*)d_in[3]; delta = (const float*)d_in[4];
        theta = (const float*)d_in[5]; gamma = (const float*)d_in[6];
        omega = (const float*)d_in[7]; rms_w = (const float*)d_in[8];
        wz_w = (const float*)d_in[9]; wz_b = (const float*)d_in[10];
        wv_w = (const float*)d_in[11]; wv_b = (const float*)d_in[12];
        wr_w = (const float*)d_in[13]; wr_b = (const float*)d_in[14];
        wh1_w = (const float*)d_in[15]; wh1_b = (const float*)d_in[16];
        wh2_w = (const float*)d_in[17];
        agam = (const float*)d_in[18]; abeta = (const float*)d_in[19];
        freqs = (const float*)d_in[20];
    }

    float* out = (float*)d_out;
    const int M = Bb * Ss;

    float *p_tsn, *p_mx, *p_z, *p_v, *p_r, *p_attn;
    cudaGetSymbolAddress((void**)&p_tsn, g_tsn);
    cudaGetSymbolAddress((void**)&p_mx, g_mx);
    cudaGetSymbolAddress((void**)&p_z, g_z);
    cudaGetSymbolAddress((void**)&p_v, g_v);
    cudaGetSymbolAddress((void**)&p_r, g_r);
    cudaGetSymbolAddress((void**)&p_attn, g_attn);

    cudaFuncSetAttribute(mma_gemm<false, false, false, true>,
                         cudaFuncAttributeMaxDynamicSharedMemorySize, MM_SMEM);
    cudaFuncSetAttribute(mma_gemm<true, false, false, true>,
                         cudaFuncAttributeMaxDynamicSharedMemorySize, MM_SMEM);
    cudaFuncSetAttribute(mma_gemm<false, false, true, true>,
                         cudaFuncAttributeMaxDynamicSharedMemorySize, MM_SMEM);
    cudaFuncSetAttribute(mma_gemm<false, true, false, false>,
                         cudaFuncAttributeMaxDynamicSharedMemorySize, MM_SMEM);

    // 1-3: timestep norm
    tsn_partial<<<(Bb * Ss * Gg) / 8, 256>>>(x);
    tsn_scan<<<Bb * Gg, 256>>>();
    tsn_norm<<<(Bb * Ss * Dd / 4) / 256, 256>>>(x, tn_w, tn_b);

    // 4-5: cema
    cema_coef<<<(Dd * EN) / 256, 256>>>(alpha, delta, theta, gamma);
    cema_scan<<<(Bb * Dd * 8) / 256, 256>>>(omega);

    // 6: mx = rmsnorm(cema)*w
    rms_mx<<<M, 256>>>(rms_w);

    // 7: z = mx @ wz_w + wz_b
    mma_gemm<false, false, false, true><<<dim3(Zz / 128, M / 128), 256, MM_SMEM>>>(
        p_mx, wz_w, wz_b, nullptr, p_z, M, Zz, Dd);

    // 8: head-RMS + gamma/beta + rotary
    qk_prep<<<M, 256>>>(freqs, agam, abeta);

    // 9-10: v = silu(tsn @ wv + b), r = silu(mx @ wr + b)
    mma_gemm<true, false, false, true><<<dim3(HDim / 128, M / 128), 256, MM_SMEM>>>(
        p_tsn, wv_w, wv_b, nullptr, p_v, M, HDim, Dd);
    mma_gemm<true, false, false, true><<<dim3(HDim / 128, M / 128), 256, MM_SMEM>>>(
        p_mx, wr_w, wr_b, nullptr, p_r, M, HDim, Dd);

    // 11-13: attention
    attn_scores<<<dim3(Ss / 64, Ss / 64, BHh), 256>>>();
    attn_softmax<<<dim3(Ss, BHh), 256>>>();
    attn_pv<<<dim3(VH / 64, Ss / 64, BHh), 256>>>(p_r);

    // 14: out = mx @ wh1 + wh1_b + x
    mma_gemm<false, false, true, true><<<dim3(Dd / 128, M / 128), 256, MM_SMEM>>>(
        p_mx, wh1_w, wh1_b, x, out, M, Dd, Dd);
    // 15: out += attn @ wh2
    mma_gemm<false, true, false, false><<<dim3(Dd / 128, M / 128), 256, MM_SMEM>>>(
        p_attn, wh2_w, nullptr, nullptr, out, M, Dd, HDim);
}

// round 4
// speedup vs baseline: 1.6329x; 1.2008x over previous
#include <cuda_runtime.h>
#include <cuda_bf16.h>
#include <mma.h>
#include <math.h>
#include <stdint.h>

using namespace nvcuda;

#define FULLMASK 0xffffffffu

// ---------------- problem constants ----------------
constexpr int Bb = 2, Ss = 2048, Dd = 2048;
constexpr int Zz = 512, HDim = 4096, Hh = 8, EN = 8;
constexpr int ZH = 64, VH = 512;
constexpr int Gg = 32, DG = 64;
constexpr int BHh = Bb * Hh;
constexpr float EPSC = 1e-5f;

// ---------------- scratch (device globals; no allocation allowed) ----------------
__device__ float g_tsn [Bb * Ss * Dd];
__device__ float g_cema[Bb * Ss * Dd];
__device__ float g_mx  [Bb * Ss * Dd];
__device__ float g_z   [Bb * Ss * Zz];
__device__ float g_v   [Bb * Ss * HDim];
__device__ float g_r   [Bb * Ss * HDim];
__device__ float g_attn[Bb * Ss * HDim];
__device__ float g_scores[(size_t)BHh * Ss * Ss];
__device__ float g_p1[Bb * Gg * Ss];
__device__ float g_p2[Bb * Gg * Ss];
__device__ float g_c1[Bb * Gg * Ss];
__device__ float g_c2[Bb * Gg * Ss];
__device__ float g_coef[6][Dd * EN];
// bf16 hi/lo Q and K-transposed
__device__ __nv_bfloat16 g_qh [BHh * Ss * ZH];
__device__ __nv_bfloat16 g_ql [BHh * Ss * ZH];
__device__ __nv_bfloat16 g_kth[BHh * ZH * Ss];
__device__ __nv_bfloat16 g_ktl[BHh * ZH * Ss];

// ---------------- helpers ----------------
__device__ __forceinline__ float sigmoidf_(float x) { return 1.f / (1.f + __expf(-x)); }

__device__ __forceinline__ void bsplit(float v, __nv_bfloat16& h, __nv_bfloat16& l) {
    h = __float2bfloat16(v);
    l = __float2bfloat16(v - __bfloat162float(h));
}

// ==================================================================
// WMMA bf16 3-product GEMM: C[M,N] = A[M,K] @ W[K,N] (+bias+resid+silu+acc)
// 128x128x32 tile, 256 threads, 8 warps (4x2), warp tile 32x64
// ==================================================================
constexpr int ALD = 40;
constexpr int BLD = 136;
constexpr int CLD = 132;
constexpr int OFF_AH = 0;
constexpr int OFF_AL = OFF_AH + 128 * ALD * 2;
constexpr int OFF_BH = OFF_AL + 128 * ALD * 2;
constexpr int OFF_BL = OFF_BH + 32 * BLD * 2;
constexpr int MM_SMEM = 128 * CLD * 4;  // 67584 (union w/ epilogue)

template <bool SILU, bool ACC, bool RESID, bool BIAS>
__global__ void __launch_bounds__(256) mma_gemm(
    const float* __restrict__ A, const float* __restrict__ W,
    const float* __restrict__ bias, const float* __restrict__ resid,
    float* __restrict__ C, int M, int N, int K) {
    extern __shared__ char sm[];
    __nv_bfloat16* Ah = (__nv_bfloat16*)(sm + OFF_AH);
    __nv_bfloat16* Al = (__nv_bfloat16*)(sm + OFF_AL);
    __nv_bfloat16* Bh = (__nv_bfloat16*)(sm + OFF_BH);
    __nv_bfloat16* Bl = (__nv_bfloat16*)(sm + OFF_BL);
    float* Ct = (float*)sm;

    const int tid = threadIdx.x;
    const int wid = tid >> 5;
    const int m0 = blockIdx.y * 128;
    const int n0 = blockIdx.x * 128;
    const int wm = (wid & 3) * 32;
    const int wn = (wid >> 2) * 64;

    const int arow = tid >> 3, ac4 = tid & 7;
    const int brow = tid >> 5, bc4 = tid & 31;

    wmma::fragment<wmma::accumulator, 16, 16, 16, float> acc[2][4];
    #pragma unroll
    for (int r = 0; r < 2; r++)
        #pragma unroll
        for (int c = 0; c < 4; c++) wmma::fill_fragment(acc[r][c], 0.f);

    const int nk = K / 32;
    float4 ra[4], rb[4];

    #pragma unroll
    for (int p = 0; p < 4; p++)
        ra[p] = *(const float4*)(A + (size_t)(m0 + arow + p * 32) * K + ac4 * 4);
    #pragma unroll
    for (int p = 0; p < 4; p++)
        rb[p] = *(const float4*)(W + (size_t)(brow + p * 8) * N + n0 + bc4 * 4);

    for (int it = 0; it < nk; it++) {
        #pragma unroll
        for (int p = 0; p < 4; p++) {
            float4 v = ra[p];
            __nv_bfloat162 h01 = __floats2bfloat162_rn(v.x, v.y);
            __nv_bfloat162 h23 = __floats2bfloat162_rn(v.z, v.w);
            __nv_bfloat162 l01 = __floats2bfloat162_rn(
                v.x - __bfloat162float(h01.x), v.y - __bfloat162float(h01.y));
            __nv_bfloat162 l23 = __floats2bfloat162_rn(
                v.z - __bfloat162float(h23.x), v.w - __bfloat162float(h23.y));
            int off = (arow + p * 32) * ALD + ac4 * 4;
            *(__nv_bfloat162*)(Ah + off) = h01;
            *(__nv_bfloat162*)(Ah + off + 2) = h23;
            *(__nv_bfloat162*)(Al + off) = l01;
            *(__nv_bfloat162*)(Al + off + 2) = l23;
        }
        #pragma unroll
        for (int p = 0; p < 4; p++) {
            float4 v = rb[p];
            __nv_bfloat162 h01 = __floats2bfloat162_rn(v.x, v.y);
            __nv_bfloat162 h23 = __floats2bfloat162_rn(v.z, v.w);
            __nv_bfloat162 l01 = __floats2bfloat162_rn(
                v.x - __bfloat162float(h01.x), v.y - __bfloat162float(h01.y));
            __nv_bfloat162 l23 = __floats2bfloat162_rn(
                v.z - __bfloat162float(h23.x), v.w - __bfloat162float(h23.y));
            int off = (brow + p * 8) * BLD + bc4 * 4;
            *(__nv_bfloat162*)(Bh + off) = h01;
            *(__nv_bfloat162*)(Bh + off + 2) = h23;
            *(__nv_bfloat162*)(Bl + off) = l01;
            *(__nv_bfloat162*)(Bl + off + 2) = l23;
        }
        __syncthreads();

        if (it + 1 < nk) {
            int k0 = (it + 1) * 32;
            #pragma unroll
            for (int p = 0; p < 4; p++)
                ra[p] = *(const float4*)(A + (size_t)(m0 + arow + p * 32) * K + k0 + ac4 * 4);
            #pragma unroll
            for (int p = 0; p < 4; p++)
                rb[p] = *(const float4*)(W + (size_t)(k0 + brow + p * 8) * N + n0 + bc4 * 4);
        }

        #pragma unroll
        for (int kk = 0; kk < 2; kk++) {
            wmma::fragment<wmma::matrix_a, 16, 16, 16, __nv_bfloat16, wmma::row_major> fah[2], fal[2];
            #pragma unroll
            for (int r = 0; r < 2; r++) {
                wmma::load_matrix_sync(fah[r], Ah + (wm + r * 16) * ALD + kk * 16, ALD);
                wmma::load_matrix_sync(fal[r], Al + (wm + r * 16) * ALD + kk * 16, ALD);
            }
            #pragma unroll
            for (int c = 0; c < 4; c++) {
                wmma::fragment<wmma::matrix_b, 16, 16, 16, __nv_bfloat16, wmma::row_major> fbh, fbl;
                wmma::load_matrix_sync(fbh, Bh + (kk * 16) * BLD + wn + c * 16, BLD);
                wmma::load_matrix_sync(fbl, Bl + (kk * 16) * BLD + wn + c * 16, BLD);
                #pragma unroll
                for (int r = 0; r < 2; r++) {
                    wmma::mma_sync(acc[r][c], fah[r], fbh, acc[r][c]);
                    wmma::mma_sync(acc[r][c], fah[r], fbl, acc[r][c]);
                    wmma::mma_sync(acc[r][c], fal[r], fbh, acc[r][c]);
                }
            }
        }
        __syncthreads();
    }

    #pragma unroll
    for (int r = 0; r < 2; r++)
        #pragma unroll
        for (int c = 0; c < 4; c++)
            wmma::store_matrix_sync(Ct + (wm + r * 16) * CLD + wn + c * 16,
                                    acc[r][c], CLD, wmma::mem_row_major);
    __syncthreads();

    #pragma unroll
    for (int i = 0; i < 16; i++) {
        int flat = i * 256 + tid;
        int row = flat >> 5, col4 = (flat & 31) * 4;
        size_t goff = (size_t)(m0 + row) * N + n0 + col4;
        float v[4];
        #pragma unroll
        for (int e = 0; e < 4; e++) {
            float cv = Ct[row * CLD + col4 + e];
            if (BIAS)  cv += bias[n0 + col4 + e];
            if (RESID) cv += resid[goff + e];
            if (SILU)  cv = cv * sigmoidf_(cv);
            if (ACC)   cv += C[goff + e];
            v[e] = cv;
        }
        float4 o; o.x = v[0]; o.y = v[1]; o.z = v[2]; o.w = v[3];
        *(float4*)(C + goff) = o;
    }
}

// ==================================================================
// PV GEMM (causal): attn[128q,128n] = P @ V, fused r-gate
// ==================================================================
__global__ void __launch_bounds__(256) pv_gemm(const float* __restrict__ rgate) {
    extern __shared__ char sm[];
    __nv_bfloat16* Ah = (__nv_bfloat16*)(sm + OFF_AH);
    __nv_bfloat16* Al = (__nv_bfloat16*)(sm + OFF_AL);
    __nv_bfloat16* Bh = (__nv_bfloat16*)(sm + OFF_BH);
    __nv_bfloat16* Bl = (__nv_bfloat16*)(sm + OFF_BL);
    float* Ct = (float*)sm;

    const int tid = threadIdx.x;
    const int wid = tid >> 5;
    const int nt = blockIdx.x, qt = blockIdx.y, bh = blockIdx.z;
    const int b = bh >> 3, h = bh & 7;
    const int wm = (wid & 3) * 32;
    const int wn = (wid >> 2) * 64;

    const float* A = g_scores + (size_t)bh * Ss * Ss + (size_t)(qt * 128) * Ss;
    const float* V = g_v + (size_t)b * Ss * HDim + h * VH + nt * 128;

    const int arow = tid >> 3, ac4 = tid & 7;
    const int brow = tid >> 5, bc4 = tid & 31;

    wmma::fragment<wmma::accumulator, 16, 16, 16, float> acc[2][4];
    #pragma unroll
    for (int r = 0; r < 2; r++)
        #pragma unroll
        for (int c = 0; c < 4; c++) wmma::fill_fragment(acc[r][c], 0.f);

    const int nk = (qt + 1) * 4;
    float4 ra[4], rb[4];

    #pragma unroll
    for (int p = 0; p < 4; p++)
        ra[p] = *(const float4*)(A + (size_t)(arow + p * 32) * Ss + ac4 * 4);
    #pragma unroll
    for (int p = 0; p < 4; p++)
        rb[p] = *(const float4*)(V + (size_t)(brow + p * 8) * HDim + bc4 * 4);

    for (int it = 0; it < nk; it++) {
        #pragma unroll
        for (int p = 0; p < 4; p++) {
            float4 v = ra[p];
            __nv_bfloat162 h01 = __floats2bfloat162_rn(v.x, v.y);
            __nv_bfloat162 h23 = __floats2bfloat162_rn(v.z, v.w);
            __nv_bfloat162 l01 = __floats2bfloat162_rn(
                v.x - __bfloat162float(h01.x), v.y - __bfloat162float(h01.y));
            __nv_bfloat162 l23 = __floats2bfloat162_rn(
                v.z - __bfloat162float(h23.x), v.w - __bfloat162float(h23.y));
            int off = (arow + p * 32) * ALD + ac4 * 4;
            *(__nv_bfloat162*)(Ah + off) = h01;
            *(__nv_bfloat162*)(Ah + off + 2) = h23;
            *(__nv_bfloat162*)(Al + off) = l01;
            *(__nv_bfloat162*)(Al + off + 2) = l23;
        }
        #pragma unroll
        for (int p = 0; p < 4; p++) {
            float4 v = rb[p];
            __nv_bfloat162 h01 = __floats2bfloat162_rn(v.x, v.y);
            __nv_bfloat162 h23 = __floats2bfloat162_rn(v.z, v.w);
            __nv_bfloat162 l01 = __floats2bfloat162_rn(
                v.x - __bfloat162float(h01.x), v.y - __bfloat162float(h01.y));
            __nv_bfloat162 l23 = __floats2bfloat162_rn(
                v.z - __bfloat162float(h23.x), v.w - __bfloat162float(h23.y));
            int off = (brow + p * 8) * BLD + bc4 * 4;
            *(__nv_bfloat162*)(Bh + off) = h01;
            *(__nv_bfloat162*)(Bh + off + 2) = h23;
            *(__nv_bfloat162*)(Bl + off) = l01;
            *(__nv_bfloat162*)(Bl + off + 2) = l23;
        }
        __syncthreads();

        if (it + 1 < nk) {
            int k0 = (it + 1) * 32;
            #pragma unroll
            for (int p = 0; p < 4; p++)
                ra[p] = *(const float4*)(A + (size_t)(arow + p * 32) * Ss + k0 + ac4 * 4);
            #pragma unroll
            for (int p = 0; p < 4; p++)
                rb[p] = *(const float4*)(V + (size_t)(k0 + brow + p * 8) * HDim + bc4 * 4);
        }

        #pragma unroll
        for (int kk = 0; kk < 2; kk++) {
            wmma::fragment<wmma::matrix_a, 16, 16, 16, __nv_bfloat16, wmma::row_major> fah[2], fal[2];
            #pragma unroll
            for (int r = 0; r < 2; r++) {
                wmma::load_matrix_sync(fah[r], Ah + (wm + r * 16) * ALD + kk * 16, ALD);
                wmma::load_matrix_sync(fal[r], Al + (wm + r * 16) * ALD + kk * 16, ALD);
            }
            #pragma unroll
            for (int c = 0; c < 4; c++) {
                wmma::fragment<wmma::matrix_b, 16, 16, 16, __nv_bfloat16, wmma::row_major> fbh, fbl;
                wmma::load_matrix_sync(fbh, Bh + (kk * 16) * BLD + wn + c * 16, BLD);
                wmma::load_matrix_sync(fbl, Bl + (kk * 16) * BLD + wn + c * 16, BLD);
                #pragma unroll
                for (int r = 0; r < 2; r++) {
                    wmma::mma_sync(acc[r][c], fah[r], fbh, acc[r][c]);
                    wmma::mma_sync(acc[r][c], fah[r], fbl, acc[r][c]);
                    wmma::mma_sync(acc[r][c], fal[r], fbh, acc[r][c]);
                }
            }
        }
        __syncthreads();
    }

    #pragma unroll
    for (int r = 0; r < 2; r++)
        #pragma unroll
        for (int c = 0; c < 4; c++)
            wmma::store_matrix_sync(Ct + (wm + r * 16) * CLD + wn + c * 16,
                                    acc[r][c], CLD, wmma::mem_row_major);
    __syncthreads();

    #pragma unroll
    for (int i = 0; i < 16; i++) {
        int flat = i * 256 + tid;
        int row = flat >> 5, col4 = (flat & 31) * 4;
        int q = qt * 128 + row;
        size_t goff = ((size_t)b * Ss + q) * HDim + h * VH + nt * 128 + col4;
        float4 rg = *(const float4*)(rgate + goff);
        float4 o;
        o.x = Ct[row * CLD + col4 + 0] * rg.x;
        o.y = Ct[row * CLD + col4 + 1] * rg.y;
        o.z = Ct[row * CLD + col4 + 2] * rg.z;
        o.w = Ct[row * CLD + col4 + 3] * rg.w;
        *(float4*)(g_attn + goff) = o;
    }
}

// ==================================================================
// Attention scores via WMMA: 128x128 causal tiles, K=64, 3-product
// ==================================================================
constexpr int SC_QLD = 72;
constexpr int SC_KLD = 136;
constexpr int SC_QH = 0;
constexpr int SC_QL = SC_QH + 128 * SC_QLD * 2;
constexpr int SC_KH = SC_QL + 128 * SC_QLD * 2;
constexpr int SC_KL = SC_KH + 64 * SC_KLD * 2;
constexpr int SC_SMEM = SC_KL + 64 * SC_KLD * 2;  // 71680

__global__ void __launch_bounds__(256) attn_scores_mma() {
    int kt = blockIdx.x, qt = blockIdx.y, bh = blockIdx.z;
    if (kt > qt) return;
    extern __shared__ char sm[];
    __nv_bfloat16* Qh = (__nv_bfloat16*)(sm + SC_QH);
    __nv_bfloat16* Ql = (__nv_bfloat16*)(sm + SC_QL);
    __nv_bfloat16* Kh = (__nv_bfloat16*)(sm + SC_KH);
    __nv_bfloat16* Kl = (__nv_bfloat16*)(sm + SC_KL);
    const int tid = threadIdx.x;
    const int wid = tid >> 5;
    const int wm = (wid & 3) * 32;
    const int wn = (wid >> 2) * 64;

    const __nv_bfloat16* qsrc_h = g_qh + ((size_t)bh * Ss + qt * 128) * ZH;
    const __nv_bfloat16* qsrc_l = g_ql + ((size_t)bh * Ss + qt * 128) * ZH;
    const __nv_bfloat16* ksrc_h = g_kth + (size_t)bh * ZH * Ss + kt * 128;
    const __nv_bfloat16* ksrc_l = g_ktl + (size_t)bh * ZH * Ss + kt * 128;

    #pragma unroll
    for (int i = 0; i < 4; i++) {
        int flat = i * 256 + tid;
        int row = flat >> 3, c8 = (flat & 7) * 8;
        *(uint4*)(Qh + row * SC_QLD + c8) = *(const uint4*)(qsrc_h + row * ZH + c8);
        *(uint4*)(Ql + row * SC_QLD + c8) = *(const uint4*)(qsrc_l + row * ZH + c8);
    }
    #pragma unroll
    for (int i = 0; i < 4; i++) {
        int flat = i * 256 + tid;
        int row = flat >> 4, c8 = (flat & 15) * 8;
        *(uint4*)(Kh + row * SC_KLD + c8) = *(const uint4*)(ksrc_h + (size_t)row * Ss + c8);
        *(uint4*)(Kl + row * SC_KLD + c8) = *(const uint4*)(ksrc_l + (size_t)row * Ss + c8);
    }
    __syncthreads();

    wmma::fragment<wmma::accumulator, 16, 16, 16, float> acc[2][4];
    #pragma unroll
    for (int r = 0; r < 2; r++)
        #pragma unroll
        for (int c = 0; c < 4; c++) wmma::fill_fragment(acc[r][c], 0.f);

    #pragma unroll
    for (int kk = 0; kk < 4; kk++) {
        wmma::fragment<wmma::matrix_a, 16, 16, 16, __nv_bfloat16, wmma::row_major> fah[2], fal[2];
        #pragma unroll
        for (int r = 0; r < 2; r++) {
            wmma::load_matrix_sync(fah[r], Qh + (wm + r * 16) * SC_QLD + kk * 16, SC_QLD);
            wmma::load_matrix_sync(fal[r], Ql + (wm + r * 16) * SC_QLD + kk * 16, SC_QLD);
        }
        #pragma unroll
        for (int c = 0; c < 4; c++) {
            wmma::fragment<wmma::matrix_b, 16, 16, 16, __nv_bfloat16, wmma::row_major> fbh, fbl;
            wmma::load_matrix_sync(fbh, Kh + (kk * 16) * SC_KLD + wn + c * 16, SC_KLD);
            wmma::load_matrix_sync(fbl, Kl + (kk * 16) * SC_KLD + wn + c * 16, SC_KLD);
            #pragma unroll
            for (int r = 0; r < 2; r++) {
                wmma::mma_sync(acc[r][c], fah[r], fbh, acc[r][c]);
                wmma::mma_sync(acc[r][c], fah[r], fbl, acc[r][c]);
                wmma::mma_sync(acc[r][c], fal[r], fbh, acc[r][c]);
            }
        }
    }

    #pragma unroll
    for (int r = 0; r < 2; r++)
        #pragma unroll
        for (int c = 0; c < 4; c++)
            wmma::store_matrix_sync(
                g_scores + ((size_t)bh * Ss + qt * 128 + wm + r * 16) * Ss + kt * 128 + wn + c * 16,
                acc[r][c], Ss, wmma::mem_row_major);
}

// ==================================================================
// Timestep norm: stage 1
// ==================================================================
__global__ void tsn_partial(const float* __restrict__ x) {
    int warp = (blockIdx.x * blockDim.x + threadIdx.x) >> 5;
    int lane = threadIdx.x & 31;
    if (warp >= Bb * Ss * Gg) return;
    int g = warp % Gg;
    int s = (warp / Gg) % Ss;
    int b = warp / (Gg * Ss);
    const float* p = x + ((size_t)(b * Ss + s)) * Dd + g * DG;
    float v0 = p[lane], v1 = p[lane + 32];
    float s1 = v0 + v1;
    float s2 = v0 * v0 + v1 * v1;
    #pragma unroll
    for (int o = 16; o; o >>= 1) {
        s1 += __shfl_down_sync(FULLMASK, s1, o);
        s2 += __shfl_down_sync(FULLMASK, s2, o);
    }
    if (lane == 0) {
        int idx = (b * Gg + g) * Ss + s;
        g_p1[idx] = s1;
        g_p2[idx] = s2;
    }
}

// ==================================================================
// Timestep norm: stage 2 — inclusive prefix scan over S per (b,g)
// ==================================================================
__global__ void tsn_scan() {
    int bg = blockIdx.x;
    int t  = threadIdx.x;
    const float* r1 = g_p1 + bg * Ss;
    const float* r2 = g_p2 + bg * Ss;
    float v1[8], v2[8];
    float a1 = 0.f, a2 = 0.f;
    #pragma unroll
    for (int i = 0; i < 8; i++) {
        a1 += r1[t * 8 + i]; v1[i] = a1;
        a2 += r2[t * 8 + i]; v2[i] = a2;
    }
    __shared__ float sh1[256], sh2[256];
    sh1[t] = a1; sh2[t] = a2;
    __syncthreads();
    for (int off = 1; off < 256; off <<= 1) {
        float b1 = 0.f, b2 = 0.f;
        if (t >= off) { b1 = sh1[t - off]; b2 = sh2[t - off]; }
        __syncthreads();
        sh1[t] += b1; sh2[t] += b2;
        __syncthreads();
    }
    float o1 = t ? sh1[t - 1] : 0.f;
    float o2 = t ? sh2[t - 1] : 0.f;
    float* w1 = g_c1 + bg * Ss;
    float* w2 = g_c2 + bg * Ss;
    #pragma unroll
    for (int i = 0; i < 8; i++) {
        w1[t * 8 + i] = v1[i] + o1;
        w2[t * 8 + i] = v2[i] + o2;
    }
}

// ==================================================================
// Timestep norm: stage 3 — elementwise normalize
// ==================================================================
__global__ void tsn_norm(const float* __restrict__ x, const float* __restrict__ w,
                         const float* __restrict__ bias) {
    int i4 = blockIdx.x * blockDim.x + threadIdx.x;
    if (i4 >= Bb * Ss * Dd / 4) return;
    int d4 = i4 % (Dd / 4);
    int s  = (i4 / (Dd / 4)) % Ss;
    int b  = i4 / (Dd / 4 * Ss);
    int d  = d4 * 4;
    int g  = d / DG;
    int ci = (b * Gg + g) * Ss + s;
    float cnt  = (float)(s + 1) * (float)DG;
    float mean = g_c1[ci] / cnt;
    float var  = g_c2[ci] / cnt - mean * mean;
    float inv  = rsqrtf(var + EPSC);
    float4 xv = *(const float4*)(x + (size_t)i4 * 4);
    float4 wv = *(const float4*)(w + d);
    float4 bv = *(const float4*)(bias + d);
    float4 o;
    o.x = (xv.x - mean) * inv * wv.x + bv.x;
    o.y = (xv.y - mean) * inv * wv.y + bv.y;
    o.z = (xv.z - mean) * inv * wv.z + bv.z;
    o.w = (xv.w - mean) * inv * wv.w + bv.w;
    *(float4*)(g_tsn + (size_t)i4 * 4) = o;
}

// ==================================================================
// CEMA coefficient precompute
// ==================================================================
__global__ void cema_coef(const float* __restrict__ alpha, const float* __restrict__ delta,
                          const float* __restrict__ theta, const float* __restrict__ gamma) {
    int i = blockIdx.x * blockDim.x + threadIdx.x;
    if (i >= Dd * EN) return;
    int d = i / EN, n = i % EN;
    float p  = 1.f / (1.f + expf(-alpha[i]));
    float qm = 1.f - p * (1.f / (1.f + expf(-delta[i])));
    float th = 1.f / (1.f + expf(-theta[d]));
    float ph = th * (2.f * 3.14159265358979323846f * (float)(n + 1) / (float)EN);
    float c = cosf(ph), s = sinf(ph);
    g_coef[0][i] = qm * c;
    g_coef[1][i] = qm * s;
    g_coef[2][i] = p * c;
    g_coef[3][i] = p * s;
    g_coef[4][i] = gamma[i * 2 + 0];
    g_coef[5][i] = gamma[i * 2 + 1];
}

// ==================================================================
// CEMA scan v2: one thread per (b,d), all 8 n-states in registers
// ==================================================================
__global__ void cema_scan2(const float* __restrict__ omega) {
    int g = blockIdx.x * blockDim.x + threadIdx.x;
    if (g >= Bb * Dd) return;
    int b = g / Dd, d = g % Dd;
    float qr[8], qi[8], ur[8], ui[8], gr[8], gi[8], hr[8], hi[8];
    #pragma unroll
    for (int n = 0; n < EN; n++) {
        int ci = d * EN + n;
        qr[n] = g_coef[0][ci]; qi[n] = g_coef[1][ci];
        ur[n] = g_coef[2][ci]; ui[n] = g_coef[3][ci];
        gr[n] = g_coef[4][ci]; gi[n] = g_coef[5][ci];
        hr[n] = 0.f; hi[n] = 0.f;
    }
    float om = omega[d];
    const float* xp = g_tsn + (size_t)b * Ss * Dd + d;
    float* op = g_cema + (size_t)b * Ss * Dd + d;
    float xv = xp[0];
    for (int t = 0; t < Ss; t++) {
        float xnext = (t + 1 < Ss) ? xp[(size_t)(t + 1) * Dd] : 0.f;
        float y = 0.f;
        #pragma unroll
        for (int n = 0; n < EN; n++) {
            float nhr = fmaf(qr[n], hr[n], fmaf(-qi[n], hi[n], ur[n] * xv));
            float nhi = fmaf(qi[n], hr[n], fmaf(qr[n], hi[n], ui[n] * xv));
            hr[n] = nhr; hi[n] = nhi;
            y = fmaf(nhr, gr[n], fmaf(nhi, gi[n], y));
        }
        op[(size_t)t * Dd] = fmaf(xv, om, y);
        xv = xnext;
    }
}

// ==================================================================
// RMSNorm over D
// ==================================================================
__global__ void rms_mx(const float* __restrict__ w) {
    int row = blockIdx.x;
    int t = threadIdx.x;
    const float* xr = g_cema + (size_t)row * Dd;
    float4 xv[2];
    float ss = 0.f;
    #pragma unroll
    for (int i = 0; i < 2; i++) {
        xv[i] = *(const float4*)(xr + (t + i * 256) * 4);
        ss += xv[i].x * xv[i].x + xv[i].y * xv[i].y + xv[i].z * xv[i].z + xv[i].w * xv[i].w;
    }
    __shared__ float sh[32];
    int lane = t & 31, wp = t >> 5;
    #pragma unroll
    for (int o = 16; o; o >>= 1) ss += __shfl_xor_sync(FULLMASK, ss, o);
    if (lane == 0) sh[wp] = ss;
    __syncthreads();
    if (wp == 0) {
        float v = (lane < 8) ? sh[lane] : 0.f;
        #pragma unroll
        for (int o = 16; o; o >>= 1) v += __shfl_xor_sync(FULLMASK, v, o);
        if (lane == 0) sh[0] = v;
    }
    __syncthreads();
    float inv = rsqrtf(sh[0] / (float)Dd + EPSC);
    float* orow = g_mx + (size_t)row * Dd;
    #pragma unroll
    for (int i = 0; i < 2; i++) {
        int c = (t + i * 256) * 4;
        float4 wv = *(const float4*)(w + c);
        float4 o;
        o.x = xv[i].x * inv * wv.x;
        o.y = xv[i].y * inv * wv.y;
        o.z = xv[i].z * inv * wv.z;
        o.w = xv[i].w * inv * wv.w;
        *(float4*)(orow + c) = o;
    }
}

// ==================================================================
// z head-RMS + gamma/beta + rotary -> bf16 hi/lo Q and K-transposed
// ==================================================================
__global__ void qk_prep(const float* __restrict__ freqs, const float* __restrict__ agam,
                        const float* __restrict__ abeta) {
    int bs = blockIdx.x;
    int h = threadIdx.x >> 5, lane = threadIdx.x & 31;
    int b = bs / Ss, s = bs % Ss;
    const float* zr = g_z + (size_t)bs * Zz + h * ZH;
    float z0 = zr[2 * lane], z1 = zr[2 * lane + 1];
    float ss = z0 * z0 + z1 * z1;
    #pragma unroll
    for (int o = 16; o; o >>= 1) ss += __shfl_xor_sync(FULLMASK, ss, o);
    float inv = rsqrtf(ss / (float)ZH + EPSC);
    z0 *= inv; z1 *= inv;
    int j = h * ZH + 2 * lane;
    const float c0 = 0.125f;
    float gq0 = (agam[j] + 1.f) * c0,      gq1 = (agam[j + 1] + 1.f) * c0;
    float gk0 = (agam[Zz + j] + 1.f) * c0, gk1 = (agam[Zz + j + 1] + 1.f) * c0;
    float q0 = z0 * gq0 + abeta[j],        q1 = z1 * gq1 + abeta[j + 1];
    float k0 = z0 * gk0 + abeta[Zz + j],   k1 = z1 * gk1 + abeta[Zz + j + 1];
    float cv = freqs[(s * 32 + lane) * 2 + 0];
    float sv = freqs[(s * 32 + lane) * 2 + 1];
    float qa = q0 * cv - q1 * sv, qb = q0 * sv + q1 * cv;
    float ka = k0 * cv - k1 * sv, kb = k0 * sv + k1 * cv;

    size_t qbase = ((size_t)(b * Hh + h) * Ss + s) * ZH + 2 * lane;
    __nv_bfloat16 ha, la, hb, lb;
    bsplit(qa, ha, la); bsplit(qb, hb, lb);
    g_qh[qbase] = ha; g_qh[qbase + 1] = hb;
    g_ql[qbase] = la; g_ql[qbase + 1] = lb;

    size_t kbase = ((size_t)(b * Hh + h) * ZH + 2 * lane) * Ss + s;
    bsplit(ka, ha, la); bsplit(kb, hb, lb);
    g_kth[kbase] = ha; g_kth[kbase + Ss] = hb;
    g_ktl[kbase] = la; g_ktl[kbase + Ss] = lb;
}

// ==================================================================
// Row softmax (causal), zero-fill to 128 granularity
// ==================================================================
__global__ void __launch_bounds__(256) attn_softmax() {
    int q = blockIdx.x, bh = blockIdx.y;
    float* row = g_scores + ((size_t)bh * Ss + q) * Ss;
    int klim = ((q >> 7) + 1) << 7;
    int t = threadIdx.x;
    int nc = (klim + 255) >> 8;
    float v[8];
    float m = -1e30f;
    for (int c = 0; c < nc; c++) {
        int idx = t + c * 256;
        v[c] = (idx <= q) ? row[idx] : -1e30f;
        m = fmaxf(m, v[c]);
    }
    __shared__ float sh[32];
    int lane = t & 31, wp = t >> 5;
    #pragma unroll
    for (int o = 16; o; o >>= 1) m = fmaxf(m, __shfl_xor_sync(FULLMASK, m, o));
    if (lane == 0) sh[wp] = m;
    __syncthreads();
    if (wp == 0) {
        float x = (lane < 8) ? sh[lane] : -1e30f;
        #pragma unroll
        for (int o = 16; o; o >>= 1) x = fmaxf(x, __shfl_xor_sync(FULLMASK, x, o));
        if (lane == 0) sh[0] = x;
    }
    __syncthreads();
    m = sh[0];
    __syncthreads();
    float sum = 0.f;
    for (int c = 0; c < nc; c++) {
        float e = __expf(v[c] - m);
        v[c] = e;
        sum += e;
    }
    #pragma unroll
    for (int o = 16; o; o >>= 1) sum += __shfl_xor_sync(FULLMASK, sum, o);
    if (lane == 0) sh[wp] = sum;
    __syncthreads();
    if (wp == 0) {
        float x = (lane < 8) ? sh[lane] : 0.f;
        #pragma unroll
        for (int o = 16; o; o >>= 1) x += __shfl_xor_sync(FULLMASK, x, o);
        if (lane == 0) sh[0] = x;
    }
    __syncthreads();
    float inv = 1.f / sh[0];
    for (int c = 0; c < nc; c++) {
        int idx = t + c * 256;
        if (idx < klim) row[idx] = (idx <= q) ? v[c] * inv : 0.f;
    }
}

// ==================================================================
// launch
// ==================================================================
extern "C" void kernel_launch(void* const* d_in, const int* in_sizes, int n_in,
                              void* d_out, int out_size) {
    const float *x, *freqs, *tn_w, *tn_b, *alpha, *delta, *theta, *gamma, *omega, *rms_w;
    const float *wz_w, *wz_b, *wv_w, *wv_b, *wr_w, *wr_b, *wh1_w, *wh1_b, *wh2_w, *agam, *abeta;

    if (in_sizes[1] == Ss * 32 * 2) {
        x = (const float*)d_in[0];  freqs = (const float*)d_in[1];
        tn_w = (const float*)d_in[2]; tn_b = (const float*)d_in[3];
        alpha = (const float*)d_in[4]; delta = (const float*)d_in[5];
        theta = (const float*)d_in[6]; gamma = (const float*)d_in[7];
        omega = (const float*)d_in[8]; rms_w = (const float*)d_in[9];
        wz_w = (const float*)d_in[10]; wz_b = (const float*)d_in[11];
        wv_w = (const float*)d_in[12]; wv_b = (const float*)d_in[13];
        wr_w = (const float*)d_in[14]; wr_b = (const float*)d_in[15];
        wh1_w = (const float*)d_in[16]; wh1_b = (const float*)d_in[17];
        wh2_w = (const float*)d_in[18];
        agam = (const float*)d_in[19]; abeta = (const float*)d_in[20];
    } else {
        x = (const float*)d_in[0];
        tn_w = (const float*)d_in[1]; tn_b = (const float*)d_in[2];
        alpha = (const float*)d_in[3]; delta = (const float*)d_in[4];
        theta = (const float*)d_in[5]; gamma = (const float*)d_in[6];
        omega = (const float*)d_in[7]; rms_w = (const float*)d_in[8];
        wz_w = (const float*)d_in[9]; wz_b = (const float*)d_in[10];
        wv_w = (const float*)d_in[11]; wv_b = (const float*)d_in[12];
        wr_w = (const float*)d_in[13]; wr_b = (const float*)d_in[14];
        wh1_w = (const float*)d_in[15]; wh1_b = (const float*)d_in[16];
        wh2_w = (const float*)d_in[17];
        agam = (const float*)d_in[18]; abeta = (const float*)d_in[19];
        freqs = (const float*)d_in[20];
    }

    float* out = (float*)d_out;
    const int M = Bb * Ss;

    float *p_tsn, *p_mx, *p_z, *p_v, *p_r, *p_attn;
    cudaGetSymbolAddress((void**)&p_tsn, g_tsn);
    cudaGetSymbolAddress((void**)&p_mx, g_mx);
    cudaGetSymbolAddress((void**)&p_z, g_z);
    cudaGetSymbolAddress((void**)&p_v, g_v);
    cudaGetSymbolAddress((void**)&p_r, g_r);
    cudaGetSymbolAddress((void**)&p_attn, g_attn);

    cudaFuncSetAttribute(mma_gemm<false, false, false, true>,
                         cudaFuncAttributeMaxDynamicSharedMemorySize, MM_SMEM);
    cudaFuncSetAttribute(mma_gemm<true, false, false, true>,
                         cudaFuncAttributeMaxDynamicSharedMemorySize, MM_SMEM);
    cudaFuncSetAttribute(mma_gemm<false, false, true, true>,
                         cudaFuncAttributeMaxDynamicSharedMemorySize, MM_SMEM);
    cudaFuncSetAttribute(mma_gemm<false, true, false, false>,
                         cudaFuncAttributeMaxDynamicSharedMemorySize, MM_SMEM);
    cudaFuncSetAttribute(pv_gemm, cudaFuncAttributeMaxDynamicSharedMemorySize, MM_SMEM);
    cudaFuncSetAttribute(attn_scores_mma, cudaFuncAttributeMaxDynamicSharedMemorySize, SC_SMEM);

    // 1-3: timestep norm
    tsn_partial<<<(Bb * Ss * Gg) / 8, 256>>>(x);
    tsn_scan<<<Bb * Gg, 256>>>();
    tsn_norm<<<(Bb * Ss * Dd / 4) / 256, 256>>>(x, tn_w, tn_b);

    // 4-5: cema
    cema_coef<<<(Dd * EN) / 256, 256>>>(alpha, delta, theta, gamma);
    cema_scan2<<<(Bb * Dd) / 256, 256>>>(omega);

    // 6: mx = rmsnorm(cema)*w
    rms_mx<<<M, 256>>>(rms_w);

    // 7: z = mx @ wz_w + wz_b
    mma_gemm<false, false, false, true><<<dim3(Zz / 128, M / 128), 256, MM_SMEM>>>(
        p_mx, wz_w, wz_b, nullptr, p_z, M, Zz, Dd);

    // 8: head-RMS + gamma/beta + rotary -> bf16 q/kT
    qk_prep<<<M, 256>>>(freqs, agam, abeta);

    // 9-10: v = silu(tsn @ wv + b), r = silu(mx @ wr + b)
    mma_gemm<true, false, false, true><<<dim3(HDim / 128, M / 128), 256, MM_SMEM>>>(
        p_tsn, wv_w, wv_b, nullptr, p_v, M, HDim, Dd);
    mma_gemm<true, false, false, true><<<dim3(HDim / 128, M / 128), 256, MM_SMEM>>>(
        p_mx, wr_w, wr_b, nullptr, p_r, M, HDim, Dd);

    // 11-13: attention (WMMA scores, softmax, WMMA PV)
    attn_scores_mma<<<dim3(Ss / 128, Ss / 128, BHh), 256, SC_SMEM>>>();
    attn_softmax<<<dim3(Ss, BHh), 256>>>();
    pv_gemm<<<dim3(VH / 128, Ss / 128, BHh), 256, MM_SMEM>>>(p_r);

    // 14: out = mx @ wh1 + wh1_b + x
    mma_gemm<false, false, true, true><<<dim3(Dd / 128, M / 128), 256, MM_SMEM>>>(
        p_mx, wh1_w, wh1_b, x, out, M, Dd, Dd);
    // 15: out += attn @ wh2
    mma_gemm<false, true, false, false><<<dim3(Dd / 128, M / 128), 256, MM_SMEM>>>(
        p_attn, wh2_w, nullptr, nullptr, out, M, Dd, HDim);
}

// round 5
// speedup vs baseline: 2.0299x; 1.2432x over previous
#include <cuda_runtime.h>
#include <cuda_bf16.h>
#include <mma.h>
#include <math.h>
#include <stdint.h>

using namespace nvcuda;

#define FULLMASK 0xffffffffu

// ---------------- problem constants ----------------
constexpr int Bb = 2, Ss = 2048, Dd = 2048;
constexpr int Zz = 512, HDim = 4096, Hh = 8, EN = 8;
constexpr int ZH = 64, VH = 512;
constexpr int Gg = 32, DG = 64;
constexpr int BHh = Bb * Hh;
constexpr float EPSC = 1e-5f;

// ---------------- scratch ----------------
__device__ float g_tsn [Bb * Ss * Dd];
__device__ float g_cema[Bb * Ss * Dd];
__device__ float g_z   [Bb * Ss * Zz];
__device__ float g_r   [Bb * Ss * HDim];
__device__ float g_scores[(size_t)BHh * Ss * Ss];
__device__ float g_p1[Bb * Gg * Ss];
__device__ float g_p2[Bb * Gg * Ss];
__device__ float g_c1[Bb * Gg * Ss];
__device__ float g_c2[Bb * Gg * Ss];
__device__ float g_coef[6][Dd * EN];

// bf16 hi/lo operands
__device__ __nv_bfloat16 g_tsnh[Bb * Ss * Dd],  g_tsnl[Bb * Ss * Dd];
__device__ __nv_bfloat16 g_mxh [Bb * Ss * Dd],  g_mxl [Bb * Ss * Dd];
__device__ __nv_bfloat16 g_vh  [Bb * Ss * HDim], g_vl [Bb * Ss * HDim];
__device__ __nv_bfloat16 g_ath [Bb * Ss * HDim], g_atl[Bb * Ss * HDim];
__device__ __nv_bfloat16 g_ph[(size_t)BHh * Ss * Ss], g_pl[(size_t)BHh * Ss * Ss];
__device__ __nv_bfloat16 g_qh [BHh * Ss * ZH],  g_ql [BHh * Ss * ZH];
__device__ __nv_bfloat16 g_kth[BHh * ZH * Ss],  g_ktl[BHh * ZH * Ss];
// weight splits
__device__ __nv_bfloat16 g_wzh [Dd * Zz],   g_wzl [Dd * Zz];
__device__ __nv_bfloat16 g_wvh [Dd * HDim], g_wvl [Dd * HDim];
__device__ __nv_bfloat16 g_wrh [Dd * HDim], g_wrl [Dd * HDim];
__device__ __nv_bfloat16 g_wh1h[Dd * Dd],   g_wh1l[Dd * Dd];
__device__ __nv_bfloat16 g_wh2h[HDim * Dd], g_wh2l[HDim * Dd];

// ---------------- helpers ----------------
__device__ __forceinline__ float sigmoidf_(float x) { return 1.f / (1.f + __expf(-x)); }

__device__ __forceinline__ void bsplit(float v, __nv_bfloat16& h, __nv_bfloat16& l) {
    h = __float2bfloat16(v);
    l = __float2bfloat16(v - __bfloat162float(h));
}

__device__ __forceinline__ uint32_t smem_u32(const void* p) {
    uint32_t a;
    asm("{ .reg .u64 t; cvta.to.shared.u64 t, %1; cvt.u32.u64 %0, t; }" : "=r"(a) : "l"(p));
    return a;
}

#define CP16(dst, src) \
    asm volatile("cp.async.cg.shared.global [%0], [%1], 16;" :: "r"(dst), "l"(src))
#define CP_COMMIT() asm volatile("cp.async.commit_group;" ::: "memory")
#define CP_WAIT0()  asm volatile("cp.async.wait_group 0;" ::: "memory")

// ---------------- split kernel (fp32 -> bf16 hi/lo), float4 granular ----------------
__global__ void splitk(const float* __restrict__ src, __nv_bfloat16* __restrict__ h,
                       __nv_bfloat16* __restrict__ l, int n4) {
    int i = blockIdx.x * blockDim.x + threadIdx.x;
    if (i >= n4) return;
    float4 v = *(const float4*)(src + (size_t)i * 4);
    __nv_bfloat16 h0, l0, h1, l1, h2, l2, h3, l3;
    bsplit(v.x, h0, l0); bsplit(v.y, h1, l1);
    bsplit(v.z, h2, l2); bsplit(v.w, h3, l3);
    __nv_bfloat162* hp = (__nv_bfloat162*)(h + (size_t)i * 4);
    __nv_bfloat162* lp = (__nv_bfloat162*)(l + (size_t)i * 4);
    hp[0] = __nv_bfloat162{h0, h1}; hp[1] = __nv_bfloat162{h2, h3};
    lp[0] = __nv_bfloat162{l0, l1}; lp[1] = __nv_bfloat162{l2, l3};
}

// ==================================================================
// hgemm: bf16 hi/lo 3-product GEMM, cp.async double-buffered
// 128x128x32 tile, 256 threads, 8 warps (4x2), warp tile 32x64
// ==================================================================
constexpr int ALD = 40;
constexpr int BLD = 136;
constexpr int CLD = 132;
constexpr int ST_AH = 0;
constexpr int ST_AL = ST_AH + 128 * ALD * 2;   // 10240
constexpr int ST_BH = ST_AL + 128 * ALD * 2;   // 20480
constexpr int ST_BL = ST_BH + 32 * BLD * 2;    // 29184
constexpr int ST_SZ = ST_BL + 32 * BLD * 2;    // 37888
constexpr int HG_SMEM = (2 * ST_SZ > 128 * CLD * 4) ? 2 * ST_SZ : 128 * CLD * 4; // 75776

struct HgArgs {
    const __nv_bfloat16 *Ah, *Al, *Bh, *Bl;
    const float *bias, *resid;
    float *C;
    __nv_bfloat16 *Ch, *Cl;
    int M, N, K;
};

__device__ __forceinline__ void hg_load_stage(
    uint32_t sb, const __nv_bfloat16* Ah, const __nv_bfloat16* Al,
    const __nv_bfloat16* Bh, const __nv_bfloat16* Bl,
    int lda, int ldb, int m0, int n0, int k0, int tid) {
    // A: 128x32 = 512 16B chunks per matrix, 2/thread
    #pragma unroll
    for (int i = 0; i < 2; i++) {
        int chunk = i * 256 + tid;
        int row = chunk >> 2, c = (chunk & 3) * 8;
        size_t go = (size_t)(m0 + row) * lda + k0 + c;
        uint32_t so = sb + (uint32_t)((row * ALD + c) * 2);
        CP16(so + ST_AH, Ah + go);
        CP16(so + ST_AL, Al + go);
    }
    // B: 32x128 = 512 chunks per matrix, 2/thread
    #pragma unroll
    for (int i = 0; i < 2; i++) {
        int chunk = i * 256 + tid;
        int row = chunk >> 4, c = (chunk & 15) * 8;
        size_t go = (size_t)(k0 + row) * ldb + n0 + c;
        uint32_t so = sb + (uint32_t)((row * BLD + c) * 2);
        CP16(so + ST_BH, Bh + go);
        CP16(so + ST_BL, Bl + go);
    }
}

template <bool SILU, bool ACC, bool RESID, bool BIAS, bool OUTHL>
__global__ void __launch_bounds__(256) hgemm(HgArgs a) {
    extern __shared__ char sm[];
    const uint32_t sb0 = smem_u32(sm);
    float* Ct = (float*)sm;
    const int tid = threadIdx.x;
    const int wid = tid >> 5;
    const int m0 = blockIdx.y * 128;
    const int n0 = blockIdx.x * 128;
    const int wm = (wid & 3) * 32;
    const int wn = (wid >> 2) * 64;

    wmma::fragment<wmma::accumulator, 16, 16, 16, float> acc[2][4];
    #pragma unroll
    for (int r = 0; r < 2; r++)
        #pragma unroll
        for (int c = 0; c < 4; c++) wmma::fill_fragment(acc[r][c], 0.f);

    const int nk = a.K / 32;
    hg_load_stage(sb0, a.Ah, a.Al, a.Bh, a.Bl, a.K, a.N, m0, n0, 0, tid);
    CP_COMMIT();

    for (int it = 0; it < nk; it++) {
        CP_WAIT0();
        __syncthreads();
        if (it + 1 < nk) {
            hg_load_stage(sb0 + ((it + 1) & 1) * ST_SZ, a.Ah, a.Al, a.Bh, a.Bl,
                          a.K, a.N, m0, n0, (it + 1) * 32, tid);
            CP_COMMIT();
        }
        char* st = sm + (it & 1) * ST_SZ;
        __nv_bfloat16* Ah = (__nv_bfloat16*)(st + ST_AH);
        __nv_bfloat16* Al = (__nv_bfloat16*)(st + ST_AL);
        __nv_bfloat16* Bh = (__nv_bfloat16*)(st + ST_BH);
        __nv_bfloat16* Bl = (__nv_bfloat16*)(st + ST_BL);
        #pragma unroll
        for (int kk = 0; kk < 2; kk++) {
            wmma::fragment<wmma::matrix_a, 16, 16, 16, __nv_bfloat16, wmma::row_major> fah[2], fal[2];
            #pragma unroll
            for (int r = 0; r < 2; r++) {
                wmma::load_matrix_sync(fah[r], Ah + (wm + r * 16) * ALD + kk * 16, ALD);
                wmma::load_matrix_sync(fal[r], Al + (wm + r * 16) * ALD + kk * 16, ALD);
            }
            #pragma unroll
            for (int c = 0; c < 4; c++) {
                wmma::fragment<wmma::matrix_b, 16, 16, 16, __nv_bfloat16, wmma::row_major> fbh, fbl;
                wmma::load_matrix_sync(fbh, Bh + (kk * 16) * BLD + wn + c * 16, BLD);
                wmma::load_matrix_sync(fbl, Bl + (kk * 16) * BLD + wn + c * 16, BLD);
                #pragma unroll
                for (int r = 0; r < 2; r++) {
                    wmma::mma_sync(acc[r][c], fah[r], fbh, acc[r][c]);
                    wmma::mma_sync(acc[r][c], fah[r], fbl, acc[r][c]);
                    wmma::mma_sync(acc[r][c], fal[r], fbh, acc[r][c]);
                }
            }
        }
        __syncthreads();
    }

    #pragma unroll
    for (int r = 0; r < 2; r++)
        #pragma unroll
        for (int c = 0; c < 4; c++)
            wmma::store_matrix_sync(Ct + (wm + r * 16) * CLD + wn + c * 16,
                                    acc[r][c], CLD, wmma::mem_row_major);
    __syncthreads();

    #pragma unroll
    for (int i = 0; i < 16; i++) {
        int flat = i * 256 + tid;
        int row = flat >> 5, col4 = (flat & 31) * 4;
        size_t goff = (size_t)(m0 + row) * a.N + n0 + col4;
        float v[4];
        #pragma unroll
        for (int e = 0; e < 4; e++) {
            float cv = Ct[row * CLD + col4 + e];
            if (BIAS)  cv += a.bias[n0 + col4 + e];
            if (RESID) cv += a.resid[goff + e];
            if (SILU)  cv = cv * sigmoidf_(cv);
            if (ACC)   cv += a.C[goff + e];
            v[e] = cv;
        }
        if (OUTHL) {
            __nv_bfloat16 h0, l0, h1, l1, h2, l2, h3, l3;
            bsplit(v[0], h0, l0); bsplit(v[1], h1, l1);
            bsplit(v[2], h2, l2); bsplit(v[3], h3, l3);
            __nv_bfloat162* hp = (__nv_bfloat162*)(a.Ch + goff);
            __nv_bfloat162* lp = (__nv_bfloat162*)(a.Cl + goff);
            hp[0] = __nv_bfloat162{h0, h1}; hp[1] = __nv_bfloat162{h2, h3};
            lp[0] = __nv_bfloat162{l0, l1}; lp[1] = __nv_bfloat162{l2, l3};
        } else {
            float4 o; o.x = v[0]; o.y = v[1]; o.z = v[2]; o.w = v[3];
            *(float4*)(a.C + goff) = o;
        }
    }
}

// ==================================================================
// pv_hgemm: attn = (P @ V) * r, P/V bf16 hi/lo, out bf16 hi/lo
// ==================================================================
__global__ void __launch_bounds__(256) pv_hgemm(const float* __restrict__ rgate) {
    extern __shared__ char sm[];
    const uint32_t sb0 = smem_u32(sm);
    float* Ct = (float*)sm;
    const int tid = threadIdx.x;
    const int wid = tid >> 5;
    const int nt = blockIdx.x, qt = blockIdx.y, bh = blockIdx.z;
    const int b = bh >> 3, h = bh & 7;
    const int wm = (wid & 3) * 32;
    const int wn = (wid >> 2) * 64;

    const __nv_bfloat16* Ph = g_ph + (size_t)bh * Ss * Ss + (size_t)(qt * 128) * Ss;
    const __nv_bfloat16* Pl = g_pl + (size_t)bh * Ss * Ss + (size_t)(qt * 128) * Ss;
    const __nv_bfloat16* Vh = g_vh + (size_t)b * Ss * HDim + h * VH + nt * 128;
    const __nv_bfloat16* Vl = g_vl + (size_t)b * Ss * HDim + h * VH + nt * 128;

    wmma::fragment<wmma::accumulator, 16, 16, 16, float> acc[2][4];
    #pragma unroll
    for (int r = 0; r < 2; r++)
        #pragma unroll
        for (int c = 0; c < 4; c++) wmma::fill_fragment(acc[r][c], 0.f);

    const int nk = (qt + 1) * 4;
    hg_load_stage(sb0, Ph, Pl, Vh, Vl, Ss, HDim, 0, 0, 0, tid);
    CP_COMMIT();

    for (int it = 0; it < nk; it++) {
        CP_WAIT0();
        __syncthreads();
        if (it + 1 < nk) {
            hg_load_stage(sb0 + ((it + 1) & 1) * ST_SZ, Ph, Pl, Vh, Vl,
                          Ss, HDim, 0, 0, (it + 1) * 32, tid);
            CP_COMMIT();
        }
        char* st = sm + (it & 1) * ST_SZ;
        __nv_bfloat16* Ah = (__nv_bfloat16*)(st + ST_AH);
        __nv_bfloat16* Al = (__nv_bfloat16*)(st + ST_AL);
        __nv_bfloat16* Bh = (__nv_bfloat16*)(st + ST_BH);
        __nv_bfloat16* Bl = (__nv_bfloat16*)(st + ST_BL);
        #pragma unroll
        for (int kk = 0; kk < 2; kk++) {
            wmma::fragment<wmma::matrix_a, 16, 16, 16, __nv_bfloat16, wmma::row_major> fah[2], fal[2];
            #pragma unroll
            for (int r = 0; r < 2; r++) {
                wmma::load_matrix_sync(fah[r], Ah + (wm + r * 16) * ALD + kk * 16, ALD);
                wmma::load_matrix_sync(fal[r], Al + (wm + r * 16) * ALD + kk * 16, ALD);
            }
            #pragma unroll
            for (int c = 0; c < 4; c++) {
                wmma::fragment<wmma::matrix_b, 16, 16, 16, __nv_bfloat16, wmma::row_major> fbh, fbl;
                wmma::load_matrix_sync(fbh, Bh + (kk * 16) * BLD + wn + c * 16, BLD);
                wmma::load_matrix_sync(fbl, Bl + (kk * 16) * BLD + wn + c * 16, BLD);
                #pragma unroll
                for (int r = 0; r < 2; r++) {
                    wmma::mma_sync(acc[r][c], fah[r], fbh, acc[r][c]);
                    wmma::mma_sync(acc[r][c], fah[r], fbl, acc[r][c]);
                    wmma::mma_sync(acc[r][c], fal[r], fbh, acc[r][c]);
                }
            }
        }
        __syncthreads();
    }

    #pragma unroll
    for (int r = 0; r < 2; r++)
        #pragma unroll
        for (int c = 0; c < 4; c++)
            wmma::store_matrix_sync(Ct + (wm + r * 16) * CLD + wn + c * 16,
                                    acc[r][c], CLD, wmma::mem_row_major);
    __syncthreads();

    #pragma unroll
    for (int i = 0; i < 16; i++) {
        int flat = i * 256 + tid;
        int row = flat >> 5, col4 = (flat & 31) * 4;
        int q = qt * 128 + row;
        size_t goff = ((size_t)b * Ss + q) * HDim + h * VH + nt * 128 + col4;
        float4 rg = *(const float4*)(rgate + goff);
        float v0 = Ct[row * CLD + col4 + 0] * rg.x;
        float v1 = Ct[row * CLD + col4 + 1] * rg.y;
        float v2 = Ct[row * CLD + col4 + 2] * rg.z;
        float v3 = Ct[row * CLD + col4 + 3] * rg.w;
        __nv_bfloat16 h0, l0, h1, l1, h2, l2, h3, l3;
        bsplit(v0, h0, l0); bsplit(v1, h1, l1);
        bsplit(v2, h2, l2); bsplit(v3, h3, l3);
        __nv_bfloat162* hp = (__nv_bfloat162*)(g_ath + goff);
        __nv_bfloat162* lp = (__nv_bfloat162*)(g_atl + goff);
        hp[0] = __nv_bfloat162{h0, h1}; hp[1] = __nv_bfloat162{h2, h3};
        lp[0] = __nv_bfloat162{l0, l1}; lp[1] = __nv_bfloat162{l2, l3};
    }
}

// ==================================================================
// Attention scores via WMMA: 128x128 causal tiles, K=64, 3-product
// ==================================================================
constexpr int SC_QLD = 72;
constexpr int SC_KLD = 136;
constexpr int SC_QH = 0;
constexpr int SC_QL = SC_QH + 128 * SC_QLD * 2;
constexpr int SC_KH = SC_QL + 128 * SC_QLD * 2;
constexpr int SC_KL = SC_KH + 64 * SC_KLD * 2;
constexpr int SC_SMEM = SC_KL + 64 * SC_KLD * 2;

__global__ void __launch_bounds__(256) attn_scores_mma() {
    int kt = blockIdx.x, qt = blockIdx.y, bh = blockIdx.z;
    if (kt > qt) return;
    extern __shared__ char sm[];
    __nv_bfloat16* Qh = (__nv_bfloat16*)(sm + SC_QH);
    __nv_bfloat16* Ql = (__nv_bfloat16*)(sm + SC_QL);
    __nv_bfloat16* Kh = (__nv_bfloat16*)(sm + SC_KH);
    __nv_bfloat16* Kl = (__nv_bfloat16*)(sm + SC_KL);
    const int tid = threadIdx.x;
    const int wid = tid >> 5;
    const int wm = (wid & 3) * 32;
    const int wn = (wid >> 2) * 64;

    const __nv_bfloat16* qsrc_h = g_qh + ((size_t)bh * Ss + qt * 128) * ZH;
    const __nv_bfloat16* qsrc_l = g_ql + ((size_t)bh * Ss + qt * 128) * ZH;
    const __nv_bfloat16* ksrc_h = g_kth + (size_t)bh * ZH * Ss + kt * 128;
    const __nv_bfloat16* ksrc_l = g_ktl + (size_t)bh * ZH * Ss + kt * 128;

    #pragma unroll
    for (int i = 0; i < 4; i++) {
        int flat = i * 256 + tid;
        int row = flat >> 3, c8 = (flat & 7) * 8;
        *(uint4*)(Qh + row * SC_QLD + c8) = *(const uint4*)(qsrc_h + row * ZH + c8);
        *(uint4*)(Ql + row * SC_QLD + c8) = *(const uint4*)(qsrc_l + row * ZH + c8);
    }
    #pragma unroll
    for (int i = 0; i < 4; i++) {
        int flat = i * 256 + tid;
        int row = flat >> 4, c8 = (flat & 15) * 8;
        *(uint4*)(Kh + row * SC_KLD + c8) = *(const uint4*)(ksrc_h + (size_t)row * Ss + c8);
        *(uint4*)(Kl + row * SC_KLD + c8) = *(const uint4*)(ksrc_l + (size_t)row * Ss + c8);
    }
    __syncthreads();

    wmma::fragment<wmma::accumulator, 16, 16, 16, float> acc[2][4];
    #pragma unroll
    for (int r = 0; r < 2; r++)
        #pragma unroll
        for (int c = 0; c < 4; c++) wmma::fill_fragment(acc[r][c], 0.f);

    #pragma unroll
    for (int kk = 0; kk < 4; kk++) {
        wmma::fragment<wmma::matrix_a, 16, 16, 16, __nv_bfloat16, wmma::row_major> fah[2], fal[2];
        #pragma unroll
        for (int r = 0; r < 2; r++) {
            wmma::load_matrix_sync(fah[r], Qh + (wm + r * 16) * SC_QLD + kk * 16, SC_QLD);
            wmma::load_matrix_sync(fal[r], Ql + (wm + r * 16) * SC_QLD + kk * 16, SC_QLD);
        }
        #pragma unroll
        for (int c = 0; c < 4; c++) {
            wmma::fragment<wmma::matrix_b, 16, 16, 16, __nv_bfloat16, wmma::row_major> fbh, fbl;
            wmma::load_matrix_sync(fbh, Kh + (kk * 16) * SC_KLD + wn + c * 16, SC_KLD);
            wmma::load_matrix_sync(fbl, Kl + (kk * 16) * SC_KLD + wn + c * 16, SC_KLD);
            #pragma unroll
            for (int r = 0; r < 2; r++) {
                wmma::mma_sync(acc[r][c], fah[r], fbh, acc[r][c]);
                wmma::mma_sync(acc[r][c], fah[r], fbl, acc[r][c]);
                wmma::mma_sync(acc[r][c], fal[r], fbh, acc[r][c]);
            }
        }
    }

    #pragma unroll
    for (int r = 0; r < 2; r++)
        #pragma unroll
        for (int c = 0; c < 4; c++)
            wmma::store_matrix_sync(
                g_scores + ((size_t)bh * Ss + qt * 128 + wm + r * 16) * Ss + kt * 128 + wn + c * 16,
                acc[r][c], Ss, wmma::mem_row_major);
}

// ==================================================================
// Timestep norm
// ==================================================================
__global__ void tsn_partial(const float* __restrict__ x) {
    int warp = (blockIdx.x * blockDim.x + threadIdx.x) >> 5;
    int lane = threadIdx.x & 31;
    if (warp >= Bb * Ss * Gg) return;
    int g = warp % Gg;
    int s = (warp / Gg) % Ss;
    int b = warp / (Gg * Ss);
    const float* p = x + ((size_t)(b * Ss + s)) * Dd + g * DG;
    float v0 = p[lane], v1 = p[lane + 32];
    float s1 = v0 + v1;
    float s2 = v0 * v0 + v1 * v1;
    #pragma unroll
    for (int o = 16; o; o >>= 1) {
        s1 += __shfl_down_sync(FULLMASK, s1, o);
        s2 += __shfl_down_sync(FULLMASK, s2, o);
    }
    if (lane == 0) {
        int idx = (b * Gg + g) * Ss + s;
        g_p1[idx] = s1;
        g_p2[idx] = s2;
    }
}

__global__ void tsn_scan() {
    int bg = blockIdx.x;
    int t  = threadIdx.x;
    const float* r1 = g_p1 + bg * Ss;
    const float* r2 = g_p2 + bg * Ss;
    float v1[8], v2[8];
    float a1 = 0.f, a2 = 0.f;
    #pragma unroll
    for (int i = 0; i < 8; i++) {
        a1 += r1[t * 8 + i]; v1[i] = a1;
        a2 += r2[t * 8 + i]; v2[i] = a2;
    }
    __shared__ float sh1[256], sh2[256];
    sh1[t] = a1; sh2[t] = a2;
    __syncthreads();
    for (int off = 1; off < 256; off <<= 1) {
        float b1 = 0.f, b2 = 0.f;
        if (t >= off) { b1 = sh1[t - off]; b2 = sh2[t - off]; }
        __syncthreads();
        sh1[t] += b1; sh2[t] += b2;
        __syncthreads();
    }
    float o1 = t ? sh1[t - 1] : 0.f;
    float o2 = t ? sh2[t - 1] : 0.f;
    float* w1 = g_c1 + bg * Ss;
    float* w2 = g_c2 + bg * Ss;
    #pragma unroll
    for (int i = 0; i < 8; i++) {
        w1[t * 8 + i] = v1[i] + o1;
        w2[t * 8 + i] = v2[i] + o2;
    }
}

__global__ void tsn_norm(const float* __restrict__ x, const float* __restrict__ w,
                         const float* __restrict__ bias) {
    int i4 = blockIdx.x * blockDim.x + threadIdx.x;
    if (i4 >= Bb * Ss * Dd / 4) return;
    int d4 = i4 % (Dd / 4);
    int s  = (i4 / (Dd / 4)) % Ss;
    int b  = i4 / (Dd / 4 * Ss);
    int d  = d4 * 4;
    int g  = d / DG;
    int ci = (b * Gg + g) * Ss + s;
    float cnt  = (float)(s + 1) * (float)DG;
    float mean = g_c1[ci] / cnt;
    float var  = g_c2[ci] / cnt - mean * mean;
    float inv  = rsqrtf(var + EPSC);
    float4 xv = *(const float4*)(x + (size_t)i4 * 4);
    float4 wv = *(const float4*)(w + d);
    float4 bv = *(const float4*)(bias + d);
    float4 o;
    o.x = (xv.x - mean) * inv * wv.x + bv.x;
    o.y = (xv.y - mean) * inv * wv.y + bv.y;
    o.z = (xv.z - mean) * inv * wv.z + bv.z;
    o.w = (xv.w - mean) * inv * wv.w + bv.w;
    *(float4*)(g_tsn + (size_t)i4 * 4) = o;
    __nv_bfloat16 h0, l0, h1, l1, h2, l2, h3, l3;
    bsplit(o.x, h0, l0); bsplit(o.y, h1, l1);
    bsplit(o.z, h2, l2); bsplit(o.w, h3, l3);
    __nv_bfloat162* hp = (__nv_bfloat162*)(g_tsnh + (size_t)i4 * 4);
    __nv_bfloat162* lp = (__nv_bfloat162*)(g_tsnl + (size_t)i4 * 4);
    hp[0] = __nv_bfloat162{h0, h1}; hp[1] = __nv_bfloat162{h2, h3};
    lp[0] = __nv_bfloat162{l0, l1}; lp[1] = __nv_bfloat162{l2, l3};
}

// ==================================================================
// CEMA
// ==================================================================
__global__ void cema_coef(const float* __restrict__ alpha, const float* __restrict__ delta,
                          const float* __restrict__ theta, const float* __restrict__ gamma) {
    int i = blockIdx.x * blockDim.x + threadIdx.x;
    if (i >= Dd * EN) return;
    int d = i / EN, n = i % EN;
    float p  = 1.f / (1.f + expf(-alpha[i]));
    float qm = 1.f - p * (1.f / (1.f + expf(-delta[i])));
    float th = 1.f / (1.f + expf(-theta[d]));
    float ph = th * (2.f * 3.14159265358979323846f * (float)(n + 1) / (float)EN);
    float c = cosf(ph), s = sinf(ph);
    g_coef[0][i] = qm * c;
    g_coef[1][i] = qm * s;
    g_coef[2][i] = p * c;
    g_coef[3][i] = p * s;
    g_coef[4][i] = gamma[i * 2 + 0];
    g_coef[5][i] = gamma[i * 2 + 1];
}

__global__ void cema_scan2(const float* __restrict__ omega) {
    int g = blockIdx.x * blockDim.x + threadIdx.x;
    if (g >= Bb * Dd) return;
    int b = g / Dd, d = g % Dd;
    float qr[8], qi[8], ur[8], ui[8], gr[8], gi[8], hr[8], hi[8];
    #pragma unroll
    for (int n = 0; n < EN; n++) {
        int ci = d * EN + n;
        qr[n] = g_coef[0][ci]; qi[n] = g_coef[1][ci];
        ur[n] = g_coef[2][ci]; ui[n] = g_coef[3][ci];
        gr[n] = g_coef[4][ci]; gi[n] = g_coef[5][ci];
        hr[n] = 0.f; hi[n] = 0.f;
    }
    float om = omega[d];
    const float* xp = g_tsn + (size_t)b * Ss * Dd + d;
    float* op = g_cema + (size_t)b * Ss * Dd + d;
    float xv = xp[0];
    for (int t = 0; t < Ss; t++) {
        float xnext = (t + 1 < Ss) ? xp[(size_t)(t + 1) * Dd] : 0.f;
        float y = 0.f;
        #pragma unroll
        for (int n = 0; n < EN; n++) {
            float nhr = fmaf(qr[n], hr[n], fmaf(-qi[n], hi[n], ur[n] * xv));
            float nhi = fmaf(qi[n], hr[n], fmaf(qr[n], hi[n], ui[n] * xv));
            hr[n] = nhr; hi[n] = nhi;
            y = fmaf(nhr, gr[n], fmaf(nhi, gi[n], y));
        }
        op[(size_t)t * Dd] = fmaf(xv, om, y);
        xv = xnext;
    }
}

// ==================================================================
// RMSNorm over D -> mx hi/lo
// ==================================================================
__global__ void rms_mx(const float* __restrict__ w) {
    int row = blockIdx.x;
    int t = threadIdx.x;
    const float* xr = g_cema + (size_t)row * Dd;
    float4 xv[2];
    float ss = 0.f;
    #pragma unroll
    for (int i = 0; i < 2; i++) {
        xv[i] = *(const float4*)(xr + (t + i * 256) * 4);
        ss += xv[i].x * xv[i].x + xv[i].y * xv[i].y + xv[i].z * xv[i].z + xv[i].w * xv[i].w;
    }
    __shared__ float sh[32];
    int lane = t & 31, wp = t >> 5;
    #pragma unroll
    for (int o = 16; o; o >>= 1) ss += __shfl_xor_sync(FULLMASK, ss, o);
    if (lane == 0) sh[wp] = ss;
    __syncthreads();
    if (wp == 0) {
        float v = (lane < 8) ? sh[lane] : 0.f;
        #pragma unroll
        for (int o = 16; o; o >>= 1) v += __shfl_xor_sync(FULLMASK, v, o);
        if (lane == 0) sh[0] = v;
    }
    __syncthreads();
    float inv = rsqrtf(sh[0] / (float)Dd + EPSC);
    #pragma unroll
    for (int i = 0; i < 2; i++) {
        int c = (t + i * 256) * 4;
        float4 wv = *(const float4*)(w + c);
        float o0 = xv[i].x * inv * wv.x;
        float o1 = xv[i].y * inv * wv.y;
        float o2 = xv[i].z * inv * wv.z;
        float o3 = xv[i].w * inv * wv.w;
        __nv_bfloat16 h0, l0, h1, l1, h2, l2, h3, l3;
        bsplit(o0, h0, l0); bsplit(o1, h1, l1);
        bsplit(o2, h2, l2); bsplit(o3, h3, l3);
        size_t off = (size_t)row * Dd + c;
        __nv_bfloat162* hp = (__nv_bfloat162*)(g_mxh + off);
        __nv_bfloat162* lp = (__nv_bfloat162*)(g_mxl + off);
        hp[0] = __nv_bfloat162{h0, h1}; hp[1] = __nv_bfloat162{h2, h3};
        lp[0] = __nv_bfloat162{l0, l1}; lp[1] = __nv_bfloat162{l2, l3};
    }
}

// ==================================================================
// z head-RMS + gamma/beta + rotary -> bf16 hi/lo Q and K-transposed
// ==================================================================
__global__ void qk_prep(const float* __restrict__ freqs, const float* __restrict__ agam,
                        const float* __restrict__ abeta) {
    int bs = blockIdx.x;
    int h = threadIdx.x >> 5, lane = threadIdx.x & 31;
    int b = bs / Ss, s = bs % Ss;
    const float* zr = g_z + (size_t)bs * Zz + h * ZH;
    float z0 = zr[2 * lane], z1 = zr[2 * lane + 1];
    float ss = z0 * z0 + z1 * z1;
    #pragma unroll
    for (int o = 16; o; o >>= 1) ss += __shfl_xor_sync(FULLMASK, ss, o);
    float inv = rsqrtf(ss / (float)ZH + EPSC);
    z0 *= inv; z1 *= inv;
    int j = h * ZH + 2 * lane;
    const float c0 = 0.125f;
    float gq0 = (agam[j] + 1.f) * c0,      gq1 = (agam[j + 1] + 1.f) * c0;
    float gk0 = (agam[Zz + j] + 1.f) * c0, gk1 = (agam[Zz + j + 1] + 1.f) * c0;
    float q0 = z0 * gq0 + abeta[j],        q1 = z1 * gq1 + abeta[j + 1];
    float k0 = z0 * gk0 + abeta[Zz + j],   k1 = z1 * gk1 + abeta[Zz + j + 1];
    float cv = freqs[(s * 32 + lane) * 2 + 0];
    float sv = freqs[(s * 32 + lane) * 2 + 1];
    float qa = q0 * cv - q1 * sv, qb = q0 * sv + q1 * cv;
    float ka = k0 * cv - k1 * sv, kb = k0 * sv + k1 * cv;

    size_t qbase = ((size_t)(b * Hh + h) * Ss + s) * ZH + 2 * lane;
    __nv_bfloat16 ha, la, hb, lb;
    bsplit(qa, ha, la); bsplit(qb, hb, lb);
    g_qh[qbase] = ha; g_qh[qbase + 1] = hb;
    g_ql[qbase] = la; g_ql[qbase + 1] = lb;

    size_t kbase = ((size_t)(b * Hh + h) * ZH + 2 * lane) * Ss + s;
    bsplit(ka, ha, la); bsplit(kb, hb, lb);
    g_kth[kbase] = ha; g_kth[kbase + Ss] = hb;
    g_ktl[kbase] = la; g_ktl[kbase + Ss] = lb;
}

// ==================================================================
// Row softmax (causal), writes bf16 hi/lo P, zero-fill to 128
// ==================================================================
__global__ void __launch_bounds__(256) attn_softmax() {
    int q = blockIdx.x, bh = blockIdx.y;
    const float* row = g_scores + ((size_t)bh * Ss + q) * Ss;
    __nv_bfloat16* ph = g_ph + ((size_t)bh * Ss + q) * Ss;
    __nv_bfloat16* pl = g_pl + ((size_t)bh * Ss + q) * Ss;
    int klim = ((q >> 7) + 1) << 7;
    int t = threadIdx.x;
    int nc = (klim + 255) >> 8;
    float v[8];
    float m = -1e30f;
    for (int c = 0; c < nc; c++) {
        int idx = t + c * 256;
        v[c] = (idx <= q) ? row[idx] : -1e30f;
        m = fmaxf(m, v[c]);
    }
    __shared__ float sh[32];
    int lane = t & 31, wp = t >> 5;
    #pragma unroll
    for (int o = 16; o; o >>= 1) m = fmaxf(m, __shfl_xor_sync(FULLMASK, m, o));
    if (lane == 0) sh[wp] = m;
    __syncthreads();
    if (wp == 0) {
        float x = (lane < 8) ? sh[lane] : -1e30f;
        #pragma unroll
        for (int o = 16; o; o >>= 1) x = fmaxf(x, __shfl_xor_sync(FULLMASK, x, o));
        if (lane == 0) sh[0] = x;
    }
    __syncthreads();
    m = sh[0];
    __syncthreads();
    float sum = 0.f;
    for (int c = 0; c < nc; c++) {
        float e = __expf(v[c] - m);
        v[c] = e;
        sum += e;
    }
    #pragma unroll
    for (int o = 16; o; o >>= 1) sum += __shfl_xor_sync(FULLMASK, sum, o);
    if (lane == 0) sh[wp] = sum;
    __syncthreads();
    if (wp == 0) {
        float x = (lane < 8) ? sh[lane] : 0.f;
        #pragma unroll
        for (int o = 16; o; o >>= 1) x += __shfl_xor_sync(FULLMASK, x, o);
        if (lane == 0) sh[0] = x;
    }
    __syncthreads();
    float inv = 1.f / sh[0];
    for (int c = 0; c < nc; c++) {
        int idx = t + c * 256;
        if (idx < klim) {
            float p = (idx <= q) ? v[c] * inv : 0.f;
            __nv_bfloat16 hh, ll;
            bsplit(p, hh, ll);
            ph[idx] = hh;
            pl[idx] = ll;
        }
    }
}

// ==================================================================
// launch
// ==================================================================
extern "C" void kernel_launch(void* const* d_in, const int* in_sizes, int n_in,
                              void* d_out, int out_size) {
    const float *x, *freqs, *tn_w, *tn_b, *alpha, *delta, *theta, *gamma, *omega, *rms_w;
    const float *wz_w, *wz_b, *wv_w, *wv_b, *wr_w, *wr_b, *wh1_w, *wh1_b, *wh2_w, *agam, *abeta;

    if (in_sizes[1] == Ss * 32 * 2) {
        x = (const float*)d_in[0];  freqs = (const float*)d_in[1];
        tn_w = (const float*)d_in[2]; tn_b = (const float*)d_in[3];
        alpha = (const float*)d_in[4]; delta = (const float*)d_in[5];
        theta = (const float*)d_in[6]; gamma = (const float*)d_in[7];
        omega = (const float*)d_in[8]; rms_w = (const float*)d_in[9];
        wz_w = (const float*)d_in[10]; wz_b = (const float*)d_in[11];
        wv_w = (const float*)d_in[12]; wv_b = (const float*)d_in[13];
        wr_w = (const float*)d_in[14]; wr_b = (const float*)d_in[15];
        wh1_w = (const float*)d_in[16]; wh1_b = (const float*)d_in[17];
        wh2_w = (const float*)d_in[18];
        agam = (const float*)d_in[19]; abeta = (const float*)d_in[20];
    } else {
        x = (const float*)d_in[0];
        tn_w = (const float*)d_in[1]; tn_b = (const float*)d_in[2];
        alpha = (const float*)d_in[3]; delta = (const float*)d_in[4];
        theta = (const float*)d_in[5]; gamma = (const float*)d_in[6];
        omega = (const float*)d_in[7]; rms_w = (const float*)d_in[8];
        wz_w = (const float*)d_in[9]; wz_b = (const float*)d_in[10];
        wv_w = (const float*)d_in[11]; wv_b = (const float*)d_in[12];
        wr_w = (const float*)d_in[13]; wr_b = (const float*)d_in[14];
        wh1_w = (const float*)d_in[15]; wh1_b = (const float*)d_in[16];
        wh2_w = (const float*)d_in[17];
        agam = (const float*)d_in[18]; abeta = (const float*)d_in[19];
        freqs = (const float*)d_in[20];
    }

    float* out = (float*)d_out;
    const int M = Bb * Ss;

    // symbol addresses
    float *p_z, *p_r;
    cudaGetSymbolAddress((void**)&p_z, g_z);
    cudaGetSymbolAddress((void**)&p_r, g_r);
    __nv_bfloat16 *p_tsnh, *p_tsnl, *p_mxh, *p_mxl, *p_vh, *p_vl, *p_ath, *p_atl;
    __nv_bfloat16 *p_wzh, *p_wzl, *p_wvh, *p_wvl, *p_wrh, *p_wrl, *p_wh1h, *p_wh1l, *p_wh2h, *p_wh2l;
    cudaGetSymbolAddress((void**)&p_tsnh, g_tsnh); cudaGetSymbolAddress((void**)&p_tsnl, g_tsnl);
    cudaGetSymbolAddress((void**)&p_mxh, g_mxh);   cudaGetSymbolAddress((void**)&p_mxl, g_mxl);
    cudaGetSymbolAddress((void**)&p_vh, g_vh);     cudaGetSymbolAddress((void**)&p_vl, g_vl);
    cudaGetSymbolAddress((void**)&p_ath, g_ath);   cudaGetSymbolAddress((void**)&p_atl, g_atl);
    cudaGetSymbolAddress((void**)&p_wzh, g_wzh);   cudaGetSymbolAddress((void**)&p_wzl, g_wzl);
    cudaGetSymbolAddress((void**)&p_wvh, g_wvh);   cudaGetSymbolAddress((void**)&p_wvl, g_wvl);
    cudaGetSymbolAddress((void**)&p_wrh, g_wrh);   cudaGetSymbolAddress((void**)&p_wrl, g_wrl);
    cudaGetSymbolAddress((void**)&p_wh1h, g_wh1h); cudaGetSymbolAddress((void**)&p_wh1l, g_wh1l);
    cudaGetSymbolAddress((void**)&p_wh2h, g_wh2h); cudaGetSymbolAddress((void**)&p_wh2l, g_wh2l);

    cudaFuncSetAttribute(hgemm<false, false, false, true, false>,
                         cudaFuncAttributeMaxDynamicSharedMemorySize, HG_SMEM);
    cudaFuncSetAttribute(hgemm<true, false, false, true, true>,
                         cudaFuncAttributeMaxDynamicSharedMemorySize, HG_SMEM);
    cudaFuncSetAttribute(hgemm<true, false, false, true, false>,
                         cudaFuncAttributeMaxDynamicSharedMemorySize, HG_SMEM);
    cudaFuncSetAttribute(hgemm<false, false, true, true, false>,
                         cudaFuncAttributeMaxDynamicSharedMemorySize, HG_SMEM);
    cudaFuncSetAttribute(hgemm<false, true, false, false, false>,
                         cudaFuncAttributeMaxDynamicSharedMemorySize, HG_SMEM);
    cudaFuncSetAttribute(pv_hgemm, cudaFuncAttributeMaxDynamicSharedMemorySize, HG_SMEM);
    cudaFuncSetAttribute(attn_scores_mma, cudaFuncAttributeMaxDynamicSharedMemorySize, SC_SMEM);

    // weight splits (independent of the rest)
    splitk<<<(Dd * Zz / 4 + 255) / 256, 256>>>(wz_w, p_wzh, p_wzl, Dd * Zz / 4);
    splitk<<<(Dd * HDim / 4 + 255) / 256, 256>>>(wv_w, p_wvh, p_wvl, Dd * HDim / 4);
    splitk<<<(Dd * HDim / 4 + 255) / 256, 256>>>(wr_w, p_wrh, p_wrl, Dd * HDim / 4);
    splitk<<<(Dd * Dd / 4 + 255) / 256, 256>>>(wh1_w, p_wh1h, p_wh1l, Dd * Dd / 4);
    splitk<<<(HDim * Dd / 4 + 255) / 256, 256>>>(wh2_w, p_wh2h, p_wh2l, HDim * Dd / 4);

    // timestep norm
    tsn_partial<<<(Bb * Ss * Gg) / 8, 256>>>(x);
    tsn_scan<<<Bb * Gg, 256>>>();
    tsn_norm<<<(Bb * Ss * Dd / 4) / 256, 256>>>(x, tn_w, tn_b);

    // cema
    cema_coef<<<(Dd * EN) / 256, 256>>>(alpha, delta, theta, gamma);
    cema_scan2<<<(Bb * Dd) / 256, 256>>>(omega);

    // mx = rmsnorm(cema)*w -> hi/lo
    rms_mx<<<M, 256>>>(rms_w);

    // z = mx @ wz + b (fp32 out)
    {
        HgArgs a = {p_mxh, p_mxl, p_wzh, p_wzl, wz_b, nullptr, p_z, nullptr, nullptr, M, Zz, Dd};
        hgemm<false, false, false, true, false><<<dim3(Zz / 128, M / 128), 256, HG_SMEM>>>(a);
    }
    qk_prep<<<M, 256>>>(freqs, agam, abeta);

    // v = silu(tsn @ wv + b) -> hi/lo ; r = silu(mx @ wr + b) -> fp32
    {
        HgArgs a = {p_tsnh, p_tsnl, p_wvh, p_wvl, wv_b, nullptr, nullptr, p_vh, p_vl, M, HDim, Dd};
        hgemm<true, false, false, true, true><<<dim3(HDim / 128, M / 128), 256, HG_SMEM>>>(a);
    }
    {
        HgArgs a = {p_mxh, p_mxl, p_wrh, p_wrl, wr_b, nullptr, p_r, nullptr, nullptr, M, HDim, Dd};
        hgemm<true, false, false, true, false><<<dim3(HDim / 128, M / 128), 256, HG_SMEM>>>(a);
    }

    // attention
    attn_scores_mma<<<dim3(Ss / 128, Ss / 128, BHh), 256, SC_SMEM>>>();
    attn_softmax<<<dim3(Ss, BHh), 256>>>();
    pv_hgemm<<<dim3(VH / 128, Ss / 128, BHh), 256, HG_SMEM>>>(p_r);

    // out = mx @ wh1 + b + x ; out += attn @ wh2
    {
        HgArgs a = {p_mxh, p_mxl, p_wh1h, p_wh1l, wh1_b, x, out, nullptr, nullptr, M, Dd, Dd};
        hgemm<false, false, true, true, false><<<dim3(Dd / 128, M / 128), 256, HG_SMEM>>>(a);
    }
    {
        HgArgs a = {p_ath, p_atl, p_wh2h, p_wh2l, nullptr, nullptr, out, nullptr, nullptr, M, Dd, HDim};
        hgemm<false, true, false, false, false><<<dim3(Dd / 128, M / 128), 256, HG_SMEM>>>(a);
    }
}